// round 7
// baseline (speedup 1.0000x reference)
#include <cuda_runtime.h>
#include <math.h>

#define BB 16
#define KK 5
#define NN 4096
#define DD 64
#define CC 16
#define BN (BB*NN)
#define EPS_LN 1e-5f
#define SCALE 0.125f

// ---------------- device scratch (allocation-free) ----------------
__device__ float g_featc[BN*CC];      // LN(feat_color)
__device__ float h_fk[BN*DD];         // LN(feat) @ w_k^T
__device__ float h_fv[BN*DD];         // LN(feat) @ w_v^T
__device__ float g_stK[BN*8];         // per (b,n): Sfk, S2fk, fk.wg0, fk.wg1, fk.bg
__device__ float g_stV[BN*8];         // same for fv
__device__ float g_fg[KK*2];          // fg_pos
__device__ float g_gsc[9];            // Sg0,Sg1,Sgb,Q00,Q01,Q11,Qb0,Qb1,Qbb
__device__ float g_E[BB*KK*NN];       // exp(logit)  (unnormalized attn)
__device__ float h_qg[BB*KK*DD];      // (q @ w_mlp) * ln_kv_g
__device__ float h_qc[BB*KK*8];       // cb, sum(qg), qg.wg0, qg.wg1, qg.bg
__device__ float g_Tp[BB*64*KK*DD];   // per-seg partials of W@fv
__device__ float g_sc[BB*64*KK*8];    // per-seg scalars: C=SumW, A=SumWgx, B=SumWgy, P=SumWmv, S=SumE
__device__ float g_Cp[BB*8*KK*CC];    // partials of attn@featc
__device__ float g_slot[BB*KK*DD];
__device__ float g_wmT[DD*DD];
__device__ float g_wresT[DD*DD];
__device__ float g_wihT[DD*3*DD];
__device__ float g_whhT[DD*3*DD];

// ---------------- prologue ----------------

// multi-role: blocks 0..KK-1 = fgpos, blocks KK.. = weight transposes + grid scalars
__global__ void k_pre(const float* __restrict__ mask,
                      const float* __restrict__ wm, const float* __restrict__ wres,
                      const float* __restrict__ wih, const float* __restrict__ whh,
                      const float* __restrict__ wgr, const float* __restrict__ bgr) {
    int bid = blockIdx.x;
    if (bid < KK){
        int k = bid, t = threadIdx.x;
        float mx = 0.f, my = 0.f, s = 0.f;
        for (int n = t; n < NN; n += 256) {
            int h = n >> 6, w = n & 63;
            float m = mask[k*NN + n];
            mx += (-1.f + 2.f*w*(1.f/63.f))*m;
            my += (-1.f + 2.f*h*(1.f/63.f))*m;
            s += m;
        }
        __shared__ float sm[3][256];
        sm[0][t]=mx; sm[1][t]=my; sm[2][t]=s; __syncthreads();
        for (int o=128;o>0;o>>=1){
            if (t<o){ sm[0][t]+=sm[0][t+o]; sm[1][t]+=sm[1][t+o]; sm[2][t]+=sm[2][t+o]; }
            __syncthreads();
        }
        if (t==0){
            float inv = 1.f/(sm[2][0]+1e-5f);
            g_fg[k*2+0]=sm[0][0]*inv; g_fg[k*2+1]=sm[1][0]*inv;
        }
        return;
    }
    int t = (bid-KK)*256 + threadIdx.x;
    if (t < 4096){
        int d = t >> 6, e = t & 63;
        g_wmT[e*64+d] = wm[t];
        g_wresT[e*64+d] = wres[t];
    }
    if (t < 192*64){
        int j = t >> 6, d = t & 63;
        g_wihT[d*192+j] = wih[t];
        g_whhT[d*192+j] = whh[t];
    }
    if (bid == KK){
        __shared__ float sm2[2][9];
        int lt = threadIdx.x;
        float p9[9] = {};
        if (lt < 64){
            float w0 = wgr[lt*4+0]-wgr[lt*4+2];
            float w1 = wgr[lt*4+1]-wgr[lt*4+3];
            float bg = bgr[lt];
            p9[0]=w0; p9[1]=w1; p9[2]=bg;
            p9[3]=w0*w0; p9[4]=w0*w1; p9[5]=w1*w1;
            p9[6]=w0*bg; p9[7]=w1*bg; p9[8]=bg*bg;
            #pragma unroll
            for (int o=16;o>0;o>>=1)
                #pragma unroll
                for (int j=0;j<9;j++) p9[j] += __shfl_xor_sync(0xffffffffu,p9[j],o);
            if ((lt&31)==0)
                #pragma unroll
                for (int j=0;j<9;j++) sm2[lt>>5][j]=p9[j];
        }
        __syncthreads();
        if (lt < 9) g_gsc[lt] = sm2[0][lt]+sm2[1][lt];
    }
}

__global__ void k_lnc(const float* __restrict__ x, const float* __restrict__ g,
                      const float* __restrict__ b) {
    int idx = blockIdx.x*256 + threadIdx.x;
    int row = idx >> 4, lane = idx & 15;
    float v = x[row*CC + lane];
    float s = v;
    #pragma unroll
    for (int o=8;o>0;o>>=1) s += __shfl_xor_sync(0xffffffffu,s,o);
    float m = s*(1.f/16.f);
    float d = v-m;
    float s2 = d*d;
    #pragma unroll
    for (int o=8;o>0;o>>=1) s2 += __shfl_xor_sync(0xffffffffu,s2,o);
    float is = rsqrtf(s2*(1.f/16.f) + EPS_LN);
    g_featc[row*CC+lane] = d*is*g[lane] + b[lane];
}

// Fused: LN(feat), GEMM vs w_k/w_v, and per-row moment stats. (validated R6)
__global__ void k3_fkfv(const float* __restrict__ feat, const float* __restrict__ lng,
                        const float* __restrict__ lnb, const float* __restrict__ wk,
                        const float* __restrict__ wv, const float* __restrict__ wgr,
                        const float* __restrict__ bgr) {
    __shared__ float As[64][65];
    __shared__ float Ws[64][65];
    __shared__ float gS[64], bS[64], w0S[64], w1S[64], bgS[64];
    int t = threadIdx.x;
    int row0 = blockIdx.x*64;
    if (t < 64){
        gS[t]=lng[t]; bS[t]=lnb[t];
        w0S[t] = wgr[t*4+0]-wgr[t*4+2];
        w1S[t] = wgr[t*4+1]-wgr[t*4+3];
        bgS[t] = bgr[t];
    }
    const float4* ag = (const float4*)(feat + (size_t)row0*64);
    #pragma unroll
    for (int i=0;i<4;i++){
        int idx4 = t + i*256;
        float4 v = ag[idx4];
        int r = idx4 >> 4, d0 = (idx4 & 15)*4;
        As[r][d0]=v.x; As[r][d0+1]=v.y; As[r][d0+2]=v.z; As[r][d0+3]=v.w;
    }
    __syncthreads();
    {   // LayerNorm rows in place: 4 threads/row
        int r = t>>2, p = t&3;
        float s = 0.f;
        #pragma unroll
        for (int i=0;i<16;i++) s += As[r][p*16+i];
        s += __shfl_xor_sync(0xffffffffu,s,1);
        s += __shfl_xor_sync(0xffffffffu,s,2);
        float m = s*(1.f/64.f);
        float s2 = 0.f;
        #pragma unroll
        for (int i=0;i<16;i++){ float d = As[r][p*16+i]-m; s2 += d*d; }
        s2 += __shfl_xor_sync(0xffffffffu,s2,1);
        s2 += __shfl_xor_sync(0xffffffffu,s2,2);
        float is = rsqrtf(s2*(1.f/64.f) + EPS_LN);
        #pragma unroll
        for (int i=0;i<16;i++){
            int e = p*16+i;
            As[r][e] = (As[r][e]-m)*is*gS[e] + bS[e];
        }
    }
    int ty = t >> 4, tx = t & 15;
    int r0 = ty*4, c0 = tx*4;
    #pragma unroll
    for (int ph=0; ph<2; ph++){
        const float4* wg = (const float4*)(ph ? wv : wk);
        __syncthreads();
        #pragma unroll
        for (int i=0;i<4;i++){
            int idx4 = t + i*256;
            float4 v = wg[idx4];
            int r = idx4 >> 4, d0 = (idx4 & 15)*4;
            Ws[r][d0]=v.x; Ws[r][d0+1]=v.y; Ws[r][d0+2]=v.z; Ws[r][d0+3]=v.w;
        }
        __syncthreads();
        float acc[4][4] = {};
        #pragma unroll 4
        for (int d=0; d<64; d++){
            float a[4], w4[4];
            #pragma unroll
            for (int i=0;i<4;i++) a[i] = As[r0+i][d];
            #pragma unroll
            for (int j=0;j<4;j++) w4[j] = Ws[c0+j][d];
            #pragma unroll
            for (int i=0;i<4;i++)
                #pragma unroll
                for (int j=0;j<4;j++) acc[i][j] += a[i]*w4[j];
        }
        float* out = ph ? h_fv : h_fk;
        #pragma unroll
        for (int i=0;i<4;i++)
            *(float4*)(out + (size_t)(row0+r0+i)*64 + c0) =
                make_float4(acc[i][0],acc[i][1],acc[i][2],acc[i][3]);
        float st[4][5];
        #pragma unroll
        for (int i=0;i<4;i++){
            float s=0.f, s2=0.f, a0=0.f, a1=0.f, ab=0.f;
            #pragma unroll
            for (int j=0;j<4;j++){
                float v = acc[i][j]; int e = c0+j;
                s += v; s2 += v*v;
                a0 += v*w0S[e]; a1 += v*w1S[e]; ab += v*bgS[e];
            }
            st[i][0]=s; st[i][1]=s2; st[i][2]=a0; st[i][3]=a1; st[i][4]=ab;
        }
        #pragma unroll
        for (int o=1;o<16;o<<=1)
            #pragma unroll
            for (int i=0;i<4;i++)
                #pragma unroll
                for (int j=0;j<5;j++)
                    st[i][j] += __shfl_xor_sync(0xffffffffu, st[i][j], o);
        if (tx==0){
            float* stg = ph ? g_stV : g_stK;
            #pragma unroll
            for (int i=0;i<4;i++){
                float* p = stg + (size_t)(row0+r0+i)*8;
                p[0]=st[i][0]; p[1]=st[i][1]; p[2]=st[i][2]; p[3]=st[i][3]; p[4]=st[i][4];
            }
        }
    }
}

// q for iteration 0, with slot init fused
__global__ void k3_q(const float* __restrict__ noise, const float* __restrict__ mu,
                     const float* __restrict__ ls,
                     const float* __restrict__ lnqg, const float* __restrict__ lnqb,
                     const float* __restrict__ wq,   const float* __restrict__ wm,
                     const float* __restrict__ bm,   const float* __restrict__ kvg,
                     const float* __restrict__ kvb,  const float* __restrict__ wgr,
                     const float* __restrict__ bgr) {
    __shared__ float WQ[64][65], WM[64][65];
    __shared__ float lnrow[4][64], qrow[4][64];
    __shared__ float red[4][2], red2[4][2];
    __shared__ float redq[4][2][5];
    int x = threadIdx.x, y = threadIdx.y;
    int t = y*64 + x;
    for (int i=t;i<4096;i+=256){ WQ[i>>6][i&63]=wq[i]; WM[i>>6][i&63]=wm[i]; }
    int row = blockIdx.x*4 + y;
    float sv = mu[x] + expf(ls[x]) * noise[row*64+x];
    g_slot[row*64+x] = sv;
    float s = sv;
    #pragma unroll
    for (int o=16;o>0;o>>=1) s += __shfl_xor_sync(0xffffffffu,s,o);
    if ((x&31)==0) red[y][x>>5]=s;
    __syncthreads();
    float m = (red[y][0]+red[y][1])*(1.f/64.f);
    float d = sv - m;
    float s2 = d*d;
    #pragma unroll
    for (int o=16;o>0;o>>=1) s2 += __shfl_xor_sync(0xffffffffu,s2,o);
    if ((x&31)==0) red2[y][x>>5]=s2;
    __syncthreads();
    float is = rsqrtf((red2[y][0]+red2[y][1])*(1.f/64.f) + EPS_LN);
    lnrow[y][x] = d*is*lnqg[x] + lnqb[x];
    __syncthreads();
    float q = 0.f;
    #pragma unroll 8
    for (int j=0;j<64;j++) q += lnrow[y][j]*WQ[x][j];
    qrow[y][x] = q;
    __syncthreads();
    float qm = 0.f;
    #pragma unroll 8
    for (int j=0;j<64;j++) qm += qrow[y][j]*WM[j][x];
    float qgv = qm*kvg[x];
    h_qg[row*64+x] = qgv;
    float w0 = wgr[x*4+0]-wgr[x*4+2];
    float w1 = wgr[x*4+1]-wgr[x*4+3];
    float c[5] = { q*bm[x] + qm*kvb[x], qgv, qgv*w0, qgv*w1, qgv*bgr[x] };
    #pragma unroll
    for (int o=16;o>0;o>>=1)
        #pragma unroll
        for (int j=0;j<5;j++) c[j] += __shfl_xor_sync(0xffffffffu,c[j],o);
    if ((x&31)==0)
        #pragma unroll
        for (int j=0;j<5;j++) redq[y][x>>5][j]=c[j];
    __syncthreads();
    if (x < 5) h_qc[row*8+x] = redq[y][0][x]+redq[y][1][x];
}

// ---------------- fused per-iteration kernel ----------------
// Per block (seg of 64 n, b): compute logits->E, W; accumulate W@fv partials (doB)
// and 5 scalar partials per k: C=SumW, A=SumW*gx, B=SumW*gy, P=SumW*mv, S=SumE.
__global__ void k5_iter(int doB) {
    __shared__ float fvS[64][68];
    __shared__ float qgS[KK][64];
    __shared__ float qcS[KK][8];
    __shared__ float fgS[KK*2];
    __shared__ float gsc[9];
    __shared__ float wSm[64];
    __shared__ float redS[KK][8][5];
    __shared__ float part[KK][64];
    int b = blockIdx.y, seg = blockIdx.x, n0 = seg*64, t = threadIdx.x;
    for (int i=t;i<KK*64;i+=256) qgS[i>>6][i&63] = h_qg[(b*KK + (i>>6))*64 + (i&63)];
    if (t < KK*8) qcS[t>>3][t&7] = h_qc[(b*KK + (t>>3))*8 + (t&7)];
    if (t < KK*2) fgS[t] = g_fg[t];
    if (t < 9) gsc[t] = g_gsc[t];
    for (int i=t;i<KK*64;i+=256) ((float*)part)[i] = 0.f;
    const float4* fvg4 = (const float4*)(h_fv + (size_t)(b*NN+n0)*64);
    #pragma unroll
    for (int i=0;i<4;i++){
        int idx4 = t + i*256;
        float4 v = fvg4[idx4];
        int r = idx4>>4, c=(idx4&15)*4;
        fvS[r][c]=v.x; fvS[r][c+1]=v.y; fvS[r][c+2]=v.z; fvS[r][c+3]=v.w;
    }
    int n = t>>2, p = t&3, ng = n0 + n;
    float4 fk4[4];
    const float4* fkg = (const float4*)(h_fk + (size_t)(b*NN+ng)*64) + p*4;
    #pragma unroll
    for (int i=0;i<4;i++) fk4[i]=fkg[i];
    float stK[5], stV[5];
    if (p==0){
        const float* sk = g_stK + (size_t)(b*NN+ng)*8;
        const float* svp = g_stV + (size_t)(b*NN+ng)*8;
        #pragma unroll
        for (int i=0;i<5;i++){ stK[i]=sk[i]; stV[i]=svp[i]; }
    }
    float gx = -1.f + 2.f*(ng & 63)*(1.f/63.f);
    float gy = -1.f + 2.f*(ng >> 6)*(1.f/63.f);
    int e = t & 63, qg_ = t >> 6;
    float accT[KK];
    for (int k=0;k<KK;k++){
        __syncthreads();
        // ---- phase A: logits ----
        float dq = 0.f;
        #pragma unroll
        for (int i=0;i<4;i++){
            int e0 = p*16 + i*4;
            dq += fk4[i].x*qgS[k][e0] + fk4[i].y*qgS[k][e0+1]
                + fk4[i].z*qgS[k][e0+2] + fk4[i].w*qgS[k][e0+3];
        }
        dq += __shfl_xor_sync(0xffffffffu,dq,1);
        dq += __shfl_xor_sync(0xffffffffu,dq,2);
        float v5[5];
        if (p==0){
            float r0 = gx - fgS[k*2+0];
            float r1 = gy - fgS[k*2+1];
            float Sge  = gsc[0]*r0 + gsc[1]*r1 + gsc[2];
            float Sge2 = gsc[3]*r0*r0 + 2.f*gsc[4]*r0*r1 + gsc[5]*r1*r1
                       + 2.f*gsc[6]*r0 + 2.f*gsc[7]*r1 + gsc[8];
            float fkge = stK[2]*r0 + stK[3]*r1 + stK[4];
            float su  = stK[0] + Sge;
            float su2 = stK[1] + 2.f*fkge + Sge2;
            float m   = su*(1.f/64.f);
            float var = su2*(1.f/64.f) - m*m;
            float is  = rsqrtf(var + EPS_LN);
            float dqf = dq + qcS[k][2]*r0 + qcS[k][3]*r1 + qcS[k][4];
            float lg  = SCALE*( is*(dqf - m*qcS[k][1]) + qcS[k][0] );
            float E   = __expf(lg);
            float fvge = stV[2]*r0 + stV[3]*r1 + stV[4];
            float svv  = stV[0] + Sge;
            float sv2  = stV[1] + 2.f*fvge + Sge2;
            float mv   = svv*(1.f/64.f);
            float varv = sv2*(1.f/64.f) - mv*mv;
            float isv  = rsqrtf(varv + EPS_LN);
            float W = E*isv;
            g_E[(size_t)(b*KK+k)*NN + ng] = E;
            wSm[n] = W;
            v5[0]=W; v5[1]=W*gx; v5[2]=W*gy; v5[3]=W*mv; v5[4]=E;
        } else { v5[0]=v5[1]=v5[2]=v5[3]=v5[4]=0.f; }
        #pragma unroll
        for (int o=4;o<32;o<<=1)
            #pragma unroll
            for (int j=0;j<5;j++) v5[j] += __shfl_xor_sync(0xffffffffu,v5[j],o);
        if ((t&31)==0)
            #pragma unroll
            for (int j=0;j<5;j++) redS[k][t>>5][j]=v5[j];
        __syncthreads();
        // ---- phase B: W @ fv (this k, this thread's e, 16 n) ----
        if (doB){
            float a = 0.f;
            #pragma unroll
            for (int i=0;i<16;i++){
                int nn = qg_*16 + i;
                a += wSm[nn]*fvS[nn][e];
            }
            accT[k] = a;
        }
    }
    __syncthreads();
    if (doB){
        for (int qq=0;qq<4;qq++){
            if (qg_==qq){
                #pragma unroll
                for (int k=0;k<KK;k++) part[k][e] += accT[k];
            }
            __syncthreads();
        }
        for (int i=t;i<KK*64;i+=256){
            int k=i>>6, ee=i&63;
            g_Tp[(size_t)((b*64+seg)*KK+k)*64 + ee] = part[k][ee];
        }
    }
    if (t < KK*5){
        int kk = t/5, j = t%5;
        float s = 0.f;
        #pragma unroll
        for (int w=0;w<8;w++) s += redS[kk][w][j];
        g_sc[(size_t)((b*64+seg)*KK+kk)*8 + j] = s;
    }
}

// slot update + fused next-iteration q
__global__ void k4_upd(const float* __restrict__ kvg, const float* __restrict__ kvb,
                       const float* __restrict__ bm,  const float* __restrict__ bih,
                       const float* __restrict__ bhh, const float* __restrict__ resg,
                       const float* __restrict__ resb,const float* __restrict__ bres,
                       const float* __restrict__ lnqg,const float* __restrict__ lnqb,
                       const float* __restrict__ wq,  const float* __restrict__ wm,
                       const float* __restrict__ wgr, const float* __restrict__ bgr) {
    __shared__ float WQ[64][65], WM[64][65];
    __shared__ float lnsum[4][64], upds[4][64], hps[4][64], lns[4][64];
    __shared__ float red[4][2], red2[4][2];
    __shared__ float redq[4][2][5];
    __shared__ float sm5[4][5];
    int x = threadIdx.x, y = threadIdx.y;
    int t = y*64 + x;
    for (int i=t;i<4096;i+=256){ WQ[i>>6][i&63]=wq[i]; WM[i>>6][i&63]=wm[i]; }
    int rrow = blockIdx.x*4 + y;
    int b = rrow/KK, k = rrow%KK;
    // scalar partial sums (warp 0 of each row)
    if (x < 32){
        float s5[5];
        const float* p1 = g_sc + (size_t)((b*64+x)*KK+k)*8;
        const float* p2 = g_sc + (size_t)((b*64+x+32)*KK+k)*8;
        #pragma unroll
        for (int j=0;j<5;j++) s5[j] = p1[j] + p2[j];
        #pragma unroll
        for (int o=16;o>0;o>>=1)
            #pragma unroll
            for (int j=0;j<5;j++) s5[j] += __shfl_xor_sync(0xffffffffu,s5[j],o);
        if (x==0)
            #pragma unroll
            for (int j=0;j<5;j++) sm5[y][j]=s5[j];
    }
    float T = 0.f;
    #pragma unroll 8
    for (int seg=0;seg<64;seg++) T += g_Tp[(size_t)((b*64+seg)*KK+k)*64 + x];
    __syncthreads();
    float C=sm5[y][0], A=sm5[y][1], Bv=sm5[y][2], P=sm5[y][3], S=sm5[y][4];
    float w0x = wgr[x*4+0]-wgr[x*4+2];
    float w1x = wgr[x*4+1]-wgr[x*4+3];
    float bgx = bgr[x];
    float fgx = g_fg[k*2+0], fgy = g_fg[k*2+1];
    T += w0x*(A - fgx*C) + w1x*(Bv - fgy*C) + bgx*C;
    T = (T - P)/S;
    lnsum[y][x] = kvg[x]*T + kvb[x];
    float hp = g_slot[rrow*64+x];
    hps[y][x] = hp;
    __syncthreads();
    float upd = bm[x];
    #pragma unroll 8
    for (int e=0;e<64;e++) upd += g_wmT[e*64+x]*lnsum[y][e];
    upds[y][x] = upd;
    __syncthreads();
    float gir = bih[x], giz = bih[64+x], gin = bih[128+x];
    float ghr = bhh[x], ghz = bhh[64+x], ghn = bhh[128+x];
    #pragma unroll 4
    for (int d=0;d<64;d++){
        float u = upds[y][d], h = hps[y][d];
        const float* wiT = g_wihT + d*192;
        const float* whT = g_whhT + d*192;
        gir += wiT[x]*u;     giz += wiT[64+x]*u;  gin += wiT[128+x]*u;
        ghr += whT[x]*h;     ghz += whT[64+x]*h;  ghn += whT[128+x]*h;
    }
    float rg = 1.f/(1.f+expf(-(gir+ghr)));
    float z  = 1.f/(1.f+expf(-(giz+ghz)));
    float nn = tanhf(gin + rg*ghn);
    float hnew = (1.f-z)*nn + z*hp;
    float s = hnew;
    #pragma unroll
    for (int o=16;o>0;o>>=1) s += __shfl_xor_sync(0xffffffffu,s,o);
    if ((x&31)==0) red[y][x>>5]=s;
    __syncthreads();
    float m = (red[y][0]+red[y][1])*(1.f/64.f);
    float dd = hnew - m;
    float s2 = dd*dd;
    #pragma unroll
    for (int o=16;o>0;o>>=1) s2 += __shfl_xor_sync(0xffffffffu,s2,o);
    if ((x&31)==0) red2[y][x>>5]=s2;
    __syncthreads();
    float is = rsqrtf((red2[y][0]+red2[y][1])*(1.f/64.f) + EPS_LN);
    lns[y][x] = dd*is*resg[x] + resb[x];
    __syncthreads();
    float outv = bres[x] + hp;
    #pragma unroll 8
    for (int e=0;e<64;e++) outv += g_wresT[e*64+x]*lns[y][e];
    g_slot[rrow*64+x] = outv;
    // ---- fused q for next iteration ----
    __syncthreads();
    float sq = outv;
    #pragma unroll
    for (int o=16;o>0;o>>=1) sq += __shfl_xor_sync(0xffffffffu,sq,o);
    if ((x&31)==0) red[y][x>>5]=sq;
    __syncthreads();
    float mq = (red[y][0]+red[y][1])*(1.f/64.f);
    float dq = outv - mq;
    float sq2 = dq*dq;
    #pragma unroll
    for (int o=16;o>0;o>>=1) sq2 += __shfl_xor_sync(0xffffffffu,sq2,o);
    if ((x&31)==0) red2[y][x>>5]=sq2;
    __syncthreads();
    float isq = rsqrtf((red2[y][0]+red2[y][1])*(1.f/64.f) + EPS_LN);
    lnsum[y][x] = dq*isq*lnqg[x] + lnqb[x];
    __syncthreads();
    float qv = 0.f;
    #pragma unroll 8
    for (int j=0;j<64;j++) qv += lnsum[y][j]*WQ[x][j];
    upds[y][x] = qv;
    __syncthreads();
    float qm = 0.f;
    #pragma unroll 8
    for (int j=0;j<64;j++) qm += upds[y][j]*WM[j][x];
    float qgv = qm*kvg[x];
    h_qg[rrow*64+x] = qgv;
    float c[5] = { qv*bm[x] + qm*kvb[x], qgv, qgv*w0x, qgv*w1x, qgv*bgr[x] };
    #pragma unroll
    for (int o=16;o>0;o>>=1)
        #pragma unroll
        for (int j=0;j<5;j++) c[j] += __shfl_xor_sync(0xffffffffu,c[j],o);
    if ((x&31)==0)
        #pragma unroll
        for (int j=0;j<5;j++) redq[y][x>>5][j]=c[j];
    __syncthreads();
    if (x < 5) h_qc[rrow*8+x] = redq[y][0][x]+redq[y][1][x];
}

// ---------------- epilogue ----------------

__global__ void k_color() {
    __shared__ float aS[KK][512];
    __shared__ float part2[16][KK][CC];
    __shared__ float iS[KK];
    __shared__ float sred[2][KK];
    int seg = blockIdx.x, b = blockIdx.y, t = threadIdx.x;
    int nbase = seg*512;
    if (t < 64){
        float s[KK];
        #pragma unroll
        for (int k=0;k<KK;k++) s[k] = g_sc[(size_t)((b*64+t)*KK+k)*8 + 4];
        #pragma unroll
        for (int o=16;o>0;o>>=1)
            #pragma unroll
            for (int k=0;k<KK;k++) s[k] += __shfl_xor_sync(0xffffffffu,s[k],o);
        if ((t&31)==0)
            #pragma unroll
            for (int k=0;k<KK;k++) sred[t>>5][k]=s[k];
    }
    __syncthreads();
    if (t < KK) iS[t] = 1.f/(sred[0][t]+sred[1][t]);
    __syncthreads();
    for (int i=t;i<KK*512;i+=256){
        int k=i>>9, n=i&511;
        aS[k][n] = g_E[(size_t)(b*KK+k)*NN + nbase+n]*iS[k];
    }
    __syncthreads();
    int c = t & 15, q = t >> 4;
    float acc[KK] = {};
    for (int n=q*32; n<q*32+32; n++){
        float fc = g_featc[(size_t)(b*NN+nbase+n)*CC + c];
        #pragma unroll
        for (int k=0;k<KK;k++) acc[k] += aS[k][n]*fc;
    }
    #pragma unroll
    for (int k=0;k<KK;k++) part2[q][k][c] = acc[k];
    __syncthreads();
    if (t < KK*CC){
        int k = t>>4, cc = t&15;
        float s = 0.f;
        #pragma unroll
        for (int qq=0;qq<16;qq++) s += part2[qq][k][cc];
        g_Cp[(size_t)((b*8+seg)*KK+k)*CC + cc] = s;
    }
}

__global__ void k_attnnorm(float* __restrict__ out) {
    int k = blockIdx.x, b = blockIdx.y, r = b*KK+k, t = threadIdx.x;
    size_t base = (size_t)r*NN;
    __shared__ float sredS[2];
    if (t < 64){
        float s = g_sc[(size_t)((b*64+t)*KK+k)*8 + 4];
        #pragma unroll
        for (int o=16;o>0;o>>=1) s += __shfl_xor_sync(0xffffffffu,s,o);
        if ((t&31)==0) sredS[t>>5]=s;
    }
    __syncthreads();
    float invS = 1.f/(sredS[0]+sredS[1]);
    float mn = 1e30f, mx = -1e30f;
    float a[16];
    #pragma unroll
    for (int j=0;j<16;j++){
        a[j] = g_E[base + j*256 + t]*invS;
        mn = fminf(mn, a[j]); mx = fmaxf(mx, a[j]);
    }
    __shared__ float sred[8], sred2[8];
    #pragma unroll
    for (int o=16;o>0;o>>=1){
        mn = fminf(mn, __shfl_xor_sync(0xffffffffu,mn,o));
        mx = fmaxf(mx, __shfl_xor_sync(0xffffffffu,mx,o));
    }
    if ((t&31)==0){ sred[t>>5]=mn; sred2[t>>5]=mx; }
    __syncthreads();
    mn = sred[0]; mx = sred2[0];
    #pragma unroll
    for (int i=1;i<8;i++){ mn = fminf(mn, sred[i]); mx = fmaxf(mx, sred2[i]); }
    float inv = 1.f/(mx-mn+1e-5f);
    #pragma unroll
    for (int j=0;j<16;j++)
        out[6560 + base + j*256 + t] = (a[j]-mn)*inv;
}

__global__ void k_outslot(float* __restrict__ out) {
    int t = threadIdx.x;
    for (int i=t; i<80*80; i+=256){
        int r = i/80, d = i%80;
        float v;
        if (d < 64) v = g_slot[r*64+d];
        else {
            int c = d-64, b = r/KK, k = r%KK;
            v = 0.f;
            #pragma unroll
            for (int seg=0;seg<8;seg++) v += g_Cp[(size_t)((b*8+seg)*KK+k)*CC + c];
        }
        out[i] = v;
    }
    if (t < 160){
        int r = t>>1, k = r%KK;
        out[6400 + t] = g_fg[k*2 + (t&1)];
    }
}

// ---------------- launch ----------------

extern "C" void kernel_launch(void* const* d_in, const int* in_sizes, int n_in,
                              void* d_out, int out_size) {
    const float* feat  = (const float*)d_in[0];
    const float* featc = (const float*)d_in[1];
    const float* mask  = (const float*)d_in[2];
    const float* noise = (const float*)d_in[3];
    const float* mu    = (const float*)d_in[4];
    const float* ls    = (const float*)d_in[5];
    const float* wgrid = (const float*)d_in[6];
    const float* bgrid = (const float*)d_in[7];
    const float* wk    = (const float*)d_in[8];
    const float* wv    = (const float*)d_in[9];
    const float* kvg   = (const float*)d_in[10];
    const float* kvb   = (const float*)d_in[11];
    const float* wmlp  = (const float*)d_in[12];
    const float* bmlp  = (const float*)d_in[13];
    const float* qg_   = (const float*)d_in[14];
    const float* qb_   = (const float*)d_in[15];
    const float* wq    = (const float*)d_in[16];
    const float* wih   = (const float*)d_in[17];
    const float* whh   = (const float*)d_in[18];
    const float* bih   = (const float*)d_in[19];
    const float* bhh   = (const float*)d_in[20];
    const float* fg_   = (const float*)d_in[21];
    const float* fb_   = (const float*)d_in[22];
    const float* cg_   = (const float*)d_in[23];
    const float* cb_   = (const float*)d_in[24];
    const float* rg_   = (const float*)d_in[25];
    const float* rb_   = (const float*)d_in[26];
    const float* wres  = (const float*)d_in[27];
    const float* bres  = (const float*)d_in[28];
    float* out = (float*)d_out;

    k_pre<<<KK+48, 256>>>(mask, wmlp, wres, wih, whh, wgrid, bgrid);
    k_lnc<<<BN/16, 256>>>(featc, cg_, cb_);
    k3_fkfv<<<BN/64, 256>>>(feat, fg_, fb_, wk, wv, wgrid, bgrid);
    k3_q<<<20, dim3(64,4)>>>(noise, mu, ls, qg_, qb_, wq, wmlp, bmlp, kvg, kvb, wgrid, bgrid);

    for (int it=0; it<4; it++){
        k5_iter<<<dim3(64, BB), 256>>>(it < 3 ? 1 : 0);
        if (it < 3){
            k4_upd<<<20, dim3(64,4)>>>(kvg, kvb, bmlp, bih, bhh, rg_, rb_, bres,
                                       qg_, qb_, wq, wmlp, wgrid, bgrid);
        }
    }
    k_color<<<dim3(8, BB), 256>>>();
    k_attnnorm<<<dim3(KK, BB), 256>>>(out);
    k_outslot<<<1, 256>>>(out);
}

// round 11
// speedup vs baseline: 1.0304x; 1.0304x over previous
#include <cuda_runtime.h>
#include <math.h>

#define BB 16
#define KK 5
#define NN 4096
#define DD 64
#define CC 16
#define BN (BB*NN)
#define EPS_LN 1e-5f
#define SCALE 0.125f
#define NBLK 148

// ---------------- device scratch (allocation-free) ----------------
__device__ float g_featc[BN*CC];
__device__ float h_fk[BN*DD];
__device__ float h_fv[BN*DD];
__device__ float g_stK[BN*8];
__device__ float g_stV[BN*8];
__device__ float g_fg[KK*2];
__device__ float g_gsc[9];
__device__ float g_E[BB*KK*NN];
__device__ float h_qg[BB*KK*DD];
__device__ float h_qc[BB*KK*8];
__device__ float g_Tp[BB*64*KK*DD];
__device__ float g_sc[BB*64*KK*8];
__device__ float g_Cp[BB*8*KK*CC];
__device__ float g_slot[BB*KK*DD];
__device__ float g_wmT[DD*DD];
__device__ float g_wresT[DD*DD];
__device__ float g_wihT[DD*3*DD];
__device__ float g_whhT[DD*3*DD];

__device__ unsigned g_gen = 0;
__device__ unsigned g_cnt = 0;

__device__ __forceinline__ void gbar() {
    __threadfence();
    __syncthreads();
    if (threadIdx.x == 0) {
        unsigned gen = atomicAdd(&g_gen, 0u);
        if (atomicAdd(&g_cnt, 1u) == (unsigned)(NBLK - 1)) {
            atomicExch(&g_cnt, 0u);
            __threadfence();
            atomicAdd(&g_gen, 1u);
        } else {
            while (atomicAdd(&g_gen, 0u) == gen) __nanosleep(64);
        }
    }
    __syncthreads();
}

// ---------------- device stage functions ----------------

__device__ void dev_fgpos(float* sm, int k, const float* __restrict__ mask) {
    int t = threadIdx.x;
    float mx = 0.f, my = 0.f, s = 0.f;
    for (int n = t; n < NN; n += 256) {
        int h = n >> 6, w = n & 63;
        float m = mask[k*NN + n];
        mx += (-1.f + 2.f*w*(1.f/63.f))*m;
        my += (-1.f + 2.f*h*(1.f/63.f))*m;
        s += m;
    }
    float* s0 = sm; float* s1 = sm+256; float* s2 = sm+512;
    s0[t]=mx; s1[t]=my; s2[t]=s; __syncthreads();
    for (int o=128;o>0;o>>=1){
        if (t<o){ s0[t]+=s0[t+o]; s1[t]+=s1[t+o]; s2[t]+=s2[t+o]; }
        __syncthreads();
    }
    if (t==0){
        float inv = 1.f/(s2[0]+1e-5f);
        g_fg[k*2+0]=s0[0]*inv; g_fg[k*2+1]=s1[0]*inv;
    }
}

__device__ void dev_transp(float* sm, int chunk,
                           const float* __restrict__ wm, const float* __restrict__ wres,
                           const float* __restrict__ wih, const float* __restrict__ whh,
                           const float* __restrict__ wgr, const float* __restrict__ bgr) {
    int t = chunk*256 + threadIdx.x;
    if (t < 4096){
        int d = t >> 6, e = t & 63;
        g_wmT[e*64+d] = wm[t];
        g_wresT[e*64+d] = wres[t];
    }
    if (t < 12288){
        int j = t >> 6, d = t & 63;
        g_wihT[d*192+j] = wih[t];
        g_whhT[d*192+j] = whh[t];
    }
    if (chunk == 0){
        float* sm2 = sm;   // [2][9]
        int lt = threadIdx.x;
        float p9[9] = {};
        if (lt < 64){
            float w0 = wgr[lt*4+0]-wgr[lt*4+2];
            float w1 = wgr[lt*4+1]-wgr[lt*4+3];
            float bg = bgr[lt];
            p9[0]=w0; p9[1]=w1; p9[2]=bg;
            p9[3]=w0*w0; p9[4]=w0*w1; p9[5]=w1*w1;
            p9[6]=w0*bg; p9[7]=w1*bg; p9[8]=bg*bg;
            #pragma unroll
            for (int o=16;o>0;o>>=1)
                #pragma unroll
                for (int j=0;j<9;j++) p9[j] += __shfl_xor_sync(0xffffffffu,p9[j],o);
            if ((lt&31)==0)
                #pragma unroll
                for (int j=0;j<9;j++) sm2[(lt>>5)*9+j]=p9[j];
        }
        __syncthreads();
        if (lt < 9) g_gsc[lt] = sm2[lt]+sm2[9+lt];
    }
}

__device__ void dev_lnc(int bid, const float* __restrict__ x, const float* __restrict__ g,
                        const float* __restrict__ b) {
    for (int base = bid*256; base < BN*CC; base += NBLK*256){
        int idx = base + threadIdx.x;
        int lane = idx & 15;
        float v = x[idx];
        float s = v;
        #pragma unroll
        for (int o=8;o>0;o>>=1) s += __shfl_xor_sync(0xffffffffu,s,o);
        float m = s*(1.f/16.f);
        float d = v-m;
        float s2 = d*d;
        #pragma unroll
        for (int o=8;o>0;o>>=1) s2 += __shfl_xor_sync(0xffffffffu,s2,o);
        float is = rsqrtf(s2*(1.f/16.f) + EPS_LN);
        g_featc[idx] = d*is*g[lane] + b[lane];
    }
}

__device__ void dev_fkfv(float* sm, int row0, const float* __restrict__ feat,
                         const float* __restrict__ lng, const float* __restrict__ lnb,
                         const float* __restrict__ wk, const float* __restrict__ wv,
                         const float* __restrict__ wgr, const float* __restrict__ bgr) {
    float* As = sm;          // [64][65]
    float* Ws = sm + 4160;   // [64][65]
    float* gS = sm + 8320; float* bS = gS+64; float* w0S = bS+64;
    float* w1S = w0S+64; float* bgS = w1S+64;
    int t = threadIdx.x;
    __syncthreads();
    if (t < 64){
        gS[t]=lng[t]; bS[t]=lnb[t];
        w0S[t] = wgr[t*4+0]-wgr[t*4+2];
        w1S[t] = wgr[t*4+1]-wgr[t*4+3];
        bgS[t] = bgr[t];
    }
    const float4* ag = (const float4*)(feat + (size_t)row0*64);
    #pragma unroll
    for (int i=0;i<4;i++){
        int idx4 = t + i*256;
        float4 v = ag[idx4];
        int r = idx4 >> 4, d0 = (idx4 & 15)*4;
        As[r*65+d0]=v.x; As[r*65+d0+1]=v.y; As[r*65+d0+2]=v.z; As[r*65+d0+3]=v.w;
    }
    __syncthreads();
    {
        int r = t>>2, p = t&3;
        float s = 0.f;
        #pragma unroll
        for (int i=0;i<16;i++) s += As[r*65+p*16+i];
        s += __shfl_xor_sync(0xffffffffu,s,1);
        s += __shfl_xor_sync(0xffffffffu,s,2);
        float m = s*(1.f/64.f);
        float s2 = 0.f;
        #pragma unroll
        for (int i=0;i<16;i++){ float d = As[r*65+p*16+i]-m; s2 += d*d; }
        s2 += __shfl_xor_sync(0xffffffffu,s2,1);
        s2 += __shfl_xor_sync(0xffffffffu,s2,2);
        float is = rsqrtf(s2*(1.f/64.f) + EPS_LN);
        #pragma unroll
        for (int i=0;i<16;i++){
            int e = p*16+i;
            As[r*65+e] = (As[r*65+e]-m)*is*gS[e] + bS[e];
        }
    }
    int ty = t >> 4, tx = t & 15;
    int r0 = ty*4, c0 = tx*4;
    #pragma unroll
    for (int ph=0; ph<2; ph++){
        const float4* wg = (const float4*)(ph ? wv : wk);
        __syncthreads();
        #pragma unroll
        for (int i=0;i<4;i++){
            int idx4 = t + i*256;
            float4 v = wg[idx4];
            int r = idx4 >> 4, d0 = (idx4 & 15)*4;
            Ws[r*65+d0]=v.x; Ws[r*65+d0+1]=v.y; Ws[r*65+d0+2]=v.z; Ws[r*65+d0+3]=v.w;
        }
        __syncthreads();
        float acc[4][4] = {};
        #pragma unroll 4
        for (int d=0; d<64; d++){
            float a[4], w4[4];
            #pragma unroll
            for (int i=0;i<4;i++) a[i] = As[(r0+i)*65+d];
            #pragma unroll
            for (int j=0;j<4;j++) w4[j] = Ws[(c0+j)*65+d];
            #pragma unroll
            for (int i=0;i<4;i++)
                #pragma unroll
                for (int j=0;j<4;j++) acc[i][j] += a[i]*w4[j];
        }
        float* out = ph ? h_fv : h_fk;
        #pragma unroll
        for (int i=0;i<4;i++)
            *(float4*)(out + (size_t)(row0+r0+i)*64 + c0) =
                make_float4(acc[i][0],acc[i][1],acc[i][2],acc[i][3]);
        float st[4][5];
        #pragma unroll
        for (int i=0;i<4;i++){
            float s=0.f, s2=0.f, a0=0.f, a1=0.f, ab=0.f;
            #pragma unroll
            for (int j=0;j<4;j++){
                float v = acc[i][j]; int e = c0+j;
                s += v; s2 += v*v;
                a0 += v*w0S[e]; a1 += v*w1S[e]; ab += v*bgS[e];
            }
            st[i][0]=s; st[i][1]=s2; st[i][2]=a0; st[i][3]=a1; st[i][4]=ab;
        }
        #pragma unroll
        for (int o=1;o<16;o<<=1)
            #pragma unroll
            for (int i=0;i<4;i++)
                #pragma unroll
                for (int j=0;j<5;j++)
                    st[i][j] += __shfl_xor_sync(0xffffffffu, st[i][j], o);
        if (tx==0){
            float* stg = ph ? g_stV : g_stK;
            #pragma unroll
            for (int i=0;i<4;i++){
                float* p = stg + (size_t)(row0+r0+i)*8;
                p[0]=st[i][0]; p[1]=st[i][1]; p[2]=st[i][2]; p[3]=st[i][3]; p[4]=st[i][4];
            }
        }
    }
}

__device__ void dev_q0(float* sm, int row0,
                       const float* __restrict__ noise, const float* __restrict__ mu,
                       const float* __restrict__ ls,
                       const float* __restrict__ lnqg, const float* __restrict__ lnqb,
                       const float* __restrict__ wq,   const float* __restrict__ wm,
                       const float* __restrict__ bm,   const float* __restrict__ kvg,
                       const float* __restrict__ kvb,  const float* __restrict__ wgr,
                       const float* __restrict__ bgr) {
    float* WQ = sm; float* WM = sm + 4160; float* AUX = sm + 8320;
    float* lnrow = AUX; float* qrow = AUX + 256;
    float* red = AUX + 1024; float* red2 = AUX + 1032; float* redq = AUX + 1040;
    int t = threadIdx.x, x = t & 63, y = t >> 6;
    __syncthreads();
    for (int i=t;i<4096;i+=256){ WQ[(i>>6)*65+(i&63)]=wq[i]; WM[(i>>6)*65+(i&63)]=wm[i]; }
    int row = row0 + y;
    float sv = mu[x] + expf(ls[x]) * noise[row*64+x];
    g_slot[row*64+x] = sv;
    float s = sv;
    #pragma unroll
    for (int o=16;o>0;o>>=1) s += __shfl_xor_sync(0xffffffffu,s,o);
    if ((x&31)==0) red[y*2+(x>>5)]=s;
    __syncthreads();
    float m = (red[y*2]+red[y*2+1])*(1.f/64.f);
    float d = sv - m;
    float s2 = d*d;
    #pragma unroll
    for (int o=16;o>0;o>>=1) s2 += __shfl_xor_sync(0xffffffffu,s2,o);
    if ((x&31)==0) red2[y*2+(x>>5)]=s2;
    __syncthreads();
    float is = rsqrtf((red2[y*2]+red2[y*2+1])*(1.f/64.f) + EPS_LN);
    lnrow[y*64+x] = d*is*lnqg[x] + lnqb[x];
    __syncthreads();
    float q = 0.f;
    #pragma unroll 8
    for (int j=0;j<64;j++) q += lnrow[y*64+j]*WQ[x*65+j];
    qrow[y*64+x] = q;
    __syncthreads();
    float qm = 0.f;
    #pragma unroll 8
    for (int j=0;j<64;j++) qm += qrow[y*64+j]*WM[j*65+x];
    float qgv = qm*kvg[x];
    h_qg[row*64+x] = qgv;
    float w0 = wgr[x*4+0]-wgr[x*4+2];
    float w1 = wgr[x*4+1]-wgr[x*4+3];
    float c[5] = { q*bm[x] + qm*kvb[x], qgv, qgv*w0, qgv*w1, qgv*bgr[x] };
    #pragma unroll
    for (int o=16;o>0;o>>=1)
        #pragma unroll
        for (int j=0;j<5;j++) c[j] += __shfl_xor_sync(0xffffffffu,c[j],o);
    if ((x&31)==0)
        #pragma unroll
        for (int j=0;j<5;j++) redq[(y*2+(x>>5))*5+j]=c[j];
    __syncthreads();
    if (x < 5) h_qc[row*8+x] = redq[(y*2)*5+x]+redq[(y*2+1)*5+x];
}

__device__ void dev_iterA(float* sm, int seg, int b, int doB) {
    float* fvS = sm;           // [64][68]
    float* qgS = sm + 4352;    // [5][64]
    float* qcS = sm + 4672;    // [5][8]
    float* fgS = sm + 4712;    // 10
    float* gsc = sm + 4722;    // 9
    float* wSm = sm + 4731;    // 64
    float* redS = sm + 4795;   // [5][8][5]
    float* part = sm + 4995;   // [5][64]
    int n0 = seg*64, t = threadIdx.x;
    __syncthreads();
    for (int i=t;i<KK*64;i+=256) qgS[i] = __ldcg(&h_qg[b*KK*64 + i]);
    if (t < KK*8) qcS[t] = __ldcg(&h_qc[b*KK*8 + t]);
    if (t < KK*2) fgS[t] = g_fg[t];
    if (t < 9) gsc[t] = g_gsc[t];
    for (int i=t;i<KK*64;i+=256) part[i] = 0.f;
    const float4* fvg4 = (const float4*)(h_fv + (size_t)(b*NN+n0)*64);
    #pragma unroll
    for (int i=0;i<4;i++){
        int idx4 = t + i*256;
        float4 v = fvg4[idx4];
        int r = idx4>>4, c=(idx4&15)*4;
        fvS[r*68+c]=v.x; fvS[r*68+c+1]=v.y; fvS[r*68+c+2]=v.z; fvS[r*68+c+3]=v.w;
    }
    int n = t>>2, p = t&3, ng = n0 + n;
    float4 fk4[4];
    const float4* fkg = (const float4*)(h_fk + (size_t)(b*NN+ng)*64) + p*4;
    #pragma unroll
    for (int i=0;i<4;i++) fk4[i]=fkg[i];
    float stK[5], stV[5];
    if (p==0){
        const float* sk = g_stK + (size_t)(b*NN+ng)*8;
        const float* svp = g_stV + (size_t)(b*NN+ng)*8;
        #pragma unroll
        for (int i=0;i<5;i++){ stK[i]=sk[i]; stV[i]=svp[i]; }
    }
    float gx = -1.f + 2.f*(ng & 63)*(1.f/63.f);
    float gy = -1.f + 2.f*(ng >> 6)*(1.f/63.f);
    int e = t & 63, qg_ = t >> 6;
    float accT[KK];
    for (int k=0;k<KK;k++){
        __syncthreads();
        float dq = 0.f;
        #pragma unroll
        for (int i=0;i<4;i++){
            int e0 = p*16 + i*4;
            dq += fk4[i].x*qgS[k*64+e0] + fk4[i].y*qgS[k*64+e0+1]
                + fk4[i].z*qgS[k*64+e0+2] + fk4[i].w*qgS[k*64+e0+3];
        }
        dq += __shfl_xor_sync(0xffffffffu,dq,1);
        dq += __shfl_xor_sync(0xffffffffu,dq,2);
        float v5[5];
        if (p==0){
            float r0 = gx - fgS[k*2+0];
            float r1 = gy - fgS[k*2+1];
            float Sge  = gsc[0]*r0 + gsc[1]*r1 + gsc[2];
            float Sge2 = gsc[3]*r0*r0 + 2.f*gsc[4]*r0*r1 + gsc[5]*r1*r1
                       + 2.f*gsc[6]*r0 + 2.f*gsc[7]*r1 + gsc[8];
            float fkge = stK[2]*r0 + stK[3]*r1 + stK[4];
            float su  = stK[0] + Sge;
            float su2 = stK[1] + 2.f*fkge + Sge2;
            float m   = su*(1.f/64.f);
            float var = su2*(1.f/64.f) - m*m;
            float is  = rsqrtf(var + EPS_LN);
            float dqf = dq + qcS[k*8+2]*r0 + qcS[k*8+3]*r1 + qcS[k*8+4];
            float lg  = SCALE*( is*(dqf - m*qcS[k*8+1]) + qcS[k*8+0] );
            float E   = __expf(lg);
            float fvge = stV[2]*r0 + stV[3]*r1 + stV[4];
            float svv  = stV[0] + Sge;
            float sv2  = stV[1] + 2.f*fvge + Sge2;
            float mv   = svv*(1.f/64.f);
            float varv = sv2*(1.f/64.f) - mv*mv;
            float isv  = rsqrtf(varv + EPS_LN);
            float W = E*isv;
            g_E[(size_t)(b*KK+k)*NN + ng] = E;
            wSm[n] = W;
            v5[0]=W; v5[1]=W*gx; v5[2]=W*gy; v5[3]=W*mv; v5[4]=E;
        } else { v5[0]=v5[1]=v5[2]=v5[3]=v5[4]=0.f; }
        #pragma unroll
        for (int o=4;o<32;o<<=1)
            #pragma unroll
            for (int j=0;j<5;j++) v5[j] += __shfl_xor_sync(0xffffffffu,v5[j],o);
        if ((t&31)==0)
            #pragma unroll
            for (int j=0;j<5;j++) redS[(k*8+(t>>5))*5+j]=v5[j];
        __syncthreads();
        if (doB){
            float a = 0.f;
            #pragma unroll
            for (int i=0;i<16;i++){
                int nn = qg_*16 + i;
                a += wSm[nn]*fvS[nn*68+e];
            }
            accT[k] = a;
        }
    }
    __syncthreads();
    if (doB){
        for (int qq=0;qq<4;qq++){
            if (qg_==qq){
                #pragma unroll
                for (int k=0;k<KK;k++) part[k*64+e] += accT[k];
            }
            __syncthreads();
        }
        for (int i=t;i<KK*64;i+=256){
            int k=i>>6, ee=i&63;
            g_Tp[(size_t)((b*64+seg)*KK+k)*64 + ee] = part[k*64+ee];
        }
    }
    if (t < KK*5){
        int kk = t/5, j = t%5;
        float s = 0.f;
        #pragma unroll
        for (int w=0;w<8;w++) s += redS[(kk*8+w)*5+j];
        g_sc[(size_t)((b*64+seg)*KK+kk)*8 + j] = s;
    }
}

__device__ void dev_upd(float* sm, int rrow0,
                        const float* __restrict__ kvg, const float* __restrict__ kvb,
                        const float* __restrict__ bm,  const float* __restrict__ bih,
                        const float* __restrict__ bhh, const float* __restrict__ resg,
                        const float* __restrict__ resb,const float* __restrict__ bres,
                        const float* __restrict__ lnqg,const float* __restrict__ lnqb,
                        const float* __restrict__ wq,  const float* __restrict__ wm,
                        const float* __restrict__ wgr, const float* __restrict__ bgr) {
    float* WQ = sm; float* WM = sm + 4160; float* AUX = sm + 8320;
    float* lnsum = AUX; float* upds = AUX+256; float* hps = AUX+512; float* lns = AUX+768;
    float* red = AUX+1024; float* red2 = AUX+1032; float* redq = AUX+1040; float* sm5 = AUX+1080;
    int t = threadIdx.x, x = t & 63, y = t >> 6;
    __syncthreads();
    for (int i=t;i<4096;i+=256){ WQ[(i>>6)*65+(i&63)]=wq[i]; WM[(i>>6)*65+(i&63)]=wm[i]; }
    int rrow = rrow0 + y;
    int b = rrow/KK, k = rrow%KK;
    if (x < 32){
        float s5[5];
        const float* p1 = g_sc + (size_t)((b*64+x)*KK+k)*8;
        const float* p2 = g_sc + (size_t)((b*64+x+32)*KK+k)*8;
        #pragma unroll
        for (int j=0;j<5;j++) s5[j] = __ldcg(p1+j) + __ldcg(p2+j);
        #pragma unroll
        for (int o=16;o>0;o>>=1)
            #pragma unroll
            for (int j=0;j<5;j++) s5[j] += __shfl_xor_sync(0xffffffffu,s5[j],o);
        if (x==0)
            #pragma unroll
            for (int j=0;j<5;j++) sm5[y*5+j]=s5[j];
    }
    float T = 0.f;
    #pragma unroll 8
    for (int seg=0;seg<64;seg++) T += __ldcg(&g_Tp[(size_t)((b*64+seg)*KK+k)*64 + x]);
    __syncthreads();
    float C=sm5[y*5+0], A=sm5[y*5+1], Bv=sm5[y*5+2], P=sm5[y*5+3], S=sm5[y*5+4];
    float w0x = wgr[x*4+0]-wgr[x*4+2];
    float w1x = wgr[x*4+1]-wgr[x*4+3];
    float bgx = bgr[x];
    float fgx = g_fg[k*2+0], fgy = g_fg[k*2+1];
    T += w0x*(A - fgx*C) + w1x*(Bv - fgy*C) + bgx*C;
    T = (T - P)/S;
    lnsum[y*64+x] = kvg[x]*T + kvb[x];
    float hp = g_slot[rrow*64+x];
    hps[y*64+x] = hp;
    __syncthreads();
    float upd = bm[x];
    #pragma unroll 8
    for (int e=0;e<64;e++) upd += g_wmT[e*64+x]*lnsum[y*64+e];
    upds[y*64+x] = upd;
    __syncthreads();
    float gir = bih[x], giz = bih[64+x], gin = bih[128+x];
    float ghr = bhh[x], ghz = bhh[64+x], ghn = bhh[128+x];
    #pragma unroll 4
    for (int d=0;d<64;d++){
        float u = upds[y*64+d], h = hps[y*64+d];
        const float* wiT = g_wihT + d*192;
        const float* whT = g_whhT + d*192;
        gir += wiT[x]*u;     giz += wiT[64+x]*u;  gin += wiT[128+x]*u;
        ghr += whT[x]*h;     ghz += whT[64+x]*h;  ghn += whT[128+x]*h;
    }
    float rg = 1.f/(1.f+expf(-(gir+ghr)));
    float z  = 1.f/(1.f+expf(-(giz+ghz)));
    float nn = tanhf(gin + rg*ghn);
    float hnew = (1.f-z)*nn + z*hp;
    float s = hnew;
    #pragma unroll
    for (int o=16;o>0;o>>=1) s += __shfl_xor_sync(0xffffffffu,s,o);
    if ((x&31)==0) red[y*2+(x>>5)]=s;
    __syncthreads();
    float m = (red[y*2]+red[y*2+1])*(1.f/64.f);
    float dd = hnew - m;
    float s2 = dd*dd;
    #pragma unroll
    for (int o=16;o>0;o>>=1) s2 += __shfl_xor_sync(0xffffffffu,s2,o);
    if ((x&31)==0) red2[y*2+(x>>5)]=s2;
    __syncthreads();
    float is = rsqrtf((red2[y*2]+red2[y*2+1])*(1.f/64.f) + EPS_LN);
    lns[y*64+x] = dd*is*resg[x] + resb[x];
    __syncthreads();
    float outv = bres[x] + hp;
    #pragma unroll 8
    for (int e=0;e<64;e++) outv += g_wresT[e*64+x]*lns[y*64+e];
    g_slot[rrow*64+x] = outv;
    __syncthreads();
    float sq = outv;
    #pragma unroll
    for (int o=16;o>0;o>>=1) sq += __shfl_xor_sync(0xffffffffu,sq,o);
    if ((x&31)==0) red[y*2+(x>>5)]=sq;
    __syncthreads();
    float mq = (red[y*2]+red[y*2+1])*(1.f/64.f);
    float dq = outv - mq;
    float sq2 = dq*dq;
    #pragma unroll
    for (int o=16;o>0;o>>=1) sq2 += __shfl_xor_sync(0xffffffffu,sq2,o);
    if ((x&31)==0) red2[y*2+(x>>5)]=sq2;
    __syncthreads();
    float isq = rsqrtf((red2[y*2]+red2[y*2+1])*(1.f/64.f) + EPS_LN);
    lnsum[y*64+x] = dq*isq*lnqg[x] + lnqb[x];
    __syncthreads();
    float qv = 0.f;
    #pragma unroll 8
    for (int j=0;j<64;j++) qv += lnsum[y*64+j]*WQ[x*65+j];
    upds[y*64+x] = qv;
    __syncthreads();
    float qm = 0.f;
    #pragma unroll 8
    for (int j=0;j<64;j++) qm += upds[y*64+j]*WM[j*65+x];
    float qgv = qm*kvg[x];
    h_qg[rrow*64+x] = qgv;
    float c[5] = { qv*bm[x] + qm*kvb[x], qgv, qgv*w0x, qgv*w1x, qgv*bgr[x] };
    #pragma unroll
    for (int o=16;o>0;o>>=1)
        #pragma unroll
        for (int j=0;j<5;j++) c[j] += __shfl_xor_sync(0xffffffffu,c[j],o);
    if ((x&31)==0)
        #pragma unroll
        for (int j=0;j<5;j++) redq[(y*2+(x>>5))*5+j]=c[j];
    __syncthreads();
    if (x < 5) h_qc[rrow*8+x] = redq[(y*2)*5+x]+redq[(y*2+1)*5+x];
}

__device__ void dev_color(float* sm, int seg, int b) {
    float* aS = sm;            // [5][512]
    float* part2 = sm + 2560;  // [16][5][16]
    float* iS = sm + 3840;     // 5
    float* sred = sm + 3845;   // [2][5]
    int t = threadIdx.x, nbase = seg*512;
    __syncthreads();
    if (t < 64){
        float s[KK];
        #pragma unroll
        for (int k=0;k<KK;k++) s[k] = __ldcg(&g_sc[(size_t)((b*64+t)*KK+k)*8 + 4]);
        #pragma unroll
        for (int o=16;o>0;o>>=1)
            #pragma unroll
            for (int k=0;k<KK;k++) s[k] += __shfl_xor_sync(0xffffffffu,s[k],o);
        if ((t&31)==0)
            #pragma unroll
            for (int k=0;k<KK;k++) sred[(t>>5)*KK+k]=s[k];
    }
    __syncthreads();
    if (t < KK) iS[t] = 1.f/(sred[t]+sred[KK+t]);
    __syncthreads();
    for (int i=t;i<KK*512;i+=256){
        int k=i>>9, n=i&511;
        aS[i] = __ldcg(&g_E[(size_t)(b*KK+k)*NN + nbase+n])*iS[k];
    }
    __syncthreads();
    int c = t & 15, q = t >> 4;
    float acc[KK] = {};
    for (int n=q*32; n<q*32+32; n++){
        float fc = g_featc[(size_t)(b*NN+nbase+n)*CC + c];
        #pragma unroll
        for (int k=0;k<KK;k++) acc[k] += aS[k*512+n]*fc;
    }
    #pragma unroll
    for (int k=0;k<KK;k++) part2[(q*KK+k)*16+c] = acc[k];
    __syncthreads();
    if (t < KK*CC){
        int k = t>>4, cc = t&15;
        float s = 0.f;
        #pragma unroll
        for (int qq=0;qq<16;qq++) s += part2[(qq*KK+k)*16+cc];
        g_Cp[(size_t)((b*8+seg)*KK+k)*CC + cc] = s;
    }
}

__device__ void dev_attnnorm(float* sm, int k, int b, float* __restrict__ out) {
    int t = threadIdx.x, r = b*KK+k;
    size_t base = (size_t)r*NN;
    float* sredS = sm;
    float* sred = sm + 2;
    float* sred2 = sm + 10;
    __syncthreads();
    if (t < 64){
        float s = __ldcg(&g_sc[(size_t)((b*64+t)*KK+k)*8 + 4]);
        #pragma unroll
        for (int o=16;o>0;o>>=1) s += __shfl_xor_sync(0xffffffffu,s,o);
        if ((t&31)==0) sredS[t>>5]=s;
    }
    __syncthreads();
    float invS = 1.f/(sredS[0]+sredS[1]);
    float mn = 1e30f, mx = -1e30f;
    float a[16];
    #pragma unroll
    for (int j=0;j<16;j++){
        a[j] = __ldcg(&g_E[base + j*256 + t])*invS;
        mn = fminf(mn, a[j]); mx = fmaxf(mx, a[j]);
    }
    #pragma unroll
    for (int o=16;o>0;o>>=1){
        mn = fminf(mn, __shfl_xor_sync(0xffffffffu,mn,o));
        mx = fmaxf(mx, __shfl_xor_sync(0xffffffffu,mx,o));
    }
    if ((t&31)==0){ sred[t>>5]=mn; sred2[t>>5]=mx; }
    __syncthreads();
    mn = sred[0]; mx = sred2[0];
    #pragma unroll
    for (int i=1;i<8;i++){ mn = fminf(mn, sred[i]); mx = fmaxf(mx, sred2[i]); }
    float inv = 1.f/(mx-mn+1e-5f);
    #pragma unroll
    for (int j=0;j<16;j++)
        out[6560 + base + j*256 + t] = (a[j]-mn)*inv;
}

__device__ void dev_outslot(float* __restrict__ out) {
    int t = threadIdx.x;
    for (int i=t; i<80*80; i+=256){
        int r = i/80, d = i%80;
        float v;
        if (d < 64) v = __ldcg(&g_slot[r*64+d]);
        else {
            int c = d-64, b = r/KK, k = r%KK;
            v = 0.f;
            #pragma unroll
            for (int seg=0;seg<8;seg++) v += __ldcg(&g_Cp[(size_t)((b*8+seg)*KK+k)*CC + c]);
        }
        out[i] = v;
    }
    if (t < 160){
        int r = t>>1, k = r%KK;
        out[6400 + t] = g_fg[k*2 + (t&1)];
    }
}

// ---------------- the single persistent kernel ----------------

__global__ void __launch_bounds__(256, 1) k_all(
    const float* feat, const float* featc, const float* mask, const float* noise,
    const float* mu, const float* ls, const float* wgrid, const float* bgrid,
    const float* wk, const float* wv, const float* kvg, const float* kvb,
    const float* wmlp, const float* bmlp, const float* qg_, const float* qb_,
    const float* wq, const float* wih, const float* whh, const float* bih,
    const float* bhh, const float* fg_, const float* fb_, const float* cg_,
    const float* cb_, const float* rg_, const float* rb_, const float* wres,
    const float* bres, float* out)
{
    __shared__ float sm[10240];
    int bid = blockIdx.x;

    // ---- stage 0: prologue ----
    for (int g = bid; g < BN/64; g += NBLK)   // 1024 tiles (R9/R10 had 256: the bug)
        dev_fkfv(sm, g*64, feat, fg_, fb_, wk, wv, wgrid, bgrid);
    __syncthreads();
    if (bid < KK)                   dev_fgpos(sm, bid, mask);
    else if (bid < KK+48)           dev_transp(sm, bid-KK, wmlp, wres, wih, whh, wgrid, bgrid);
    else if (bid >= 60 && bid < 80) dev_q0(sm, (bid-60)*4, noise, mu, ls, qg_, qb_, wq,
                                           wmlp, bmlp, kvg, kvb, wgrid, bgrid);
    dev_lnc(bid, featc, cg_, cb_);
    gbar();

    // ---- iterations ----
    for (int it = 0; it < 4; it++){
        int doB = (it < 3) ? 1 : 0;
        for (int u = bid; u < 1024; u += NBLK)
            dev_iterA(sm, u & 63, u >> 6, doB);
        gbar();
        if (it < 3){
            if (bid < 20)
                dev_upd(sm, bid*4, kvg, kvb, bmlp, bih, bhh, rg_, rb_, bres,
                        qg_, qb_, wq, wmlp, wgrid, bgrid);
            gbar();
        }
    }

    // ---- epilogue ----
    if (bid < 128) dev_color(sm, bid & 7, bid >> 3);
    {
        int u = (bid >= 128) ? (bid - 128) : (bid + 20);
        if (u < 80) dev_attnnorm(sm, u % KK, u / KK, out);
    }
    gbar();
    if (bid == 0) dev_outslot(out);
}

// ---------------- launch ----------------

extern "C" void kernel_launch(void* const* d_in, const int* in_sizes, int n_in,
                              void* d_out, int out_size) {
    const float* feat  = (const float*)d_in[0];
    const float* featc = (const float*)d_in[1];
    const float* mask  = (const float*)d_in[2];
    const float* noise = (const float*)d_in[3];
    const float* mu    = (const float*)d_in[4];
    const float* ls    = (const float*)d_in[5];
    const float* wgrid = (const float*)d_in[6];
    const float* bgrid = (const float*)d_in[7];
    const float* wk    = (const float*)d_in[8];
    const float* wv    = (const float*)d_in[9];
    const float* kvg   = (const float*)d_in[10];
    const float* kvb   = (const float*)d_in[11];
    const float* wmlp  = (const float*)d_in[12];
    const float* bmlp  = (const float*)d_in[13];
    const float* qg_   = (const float*)d_in[14];
    const float* qb_   = (const float*)d_in[15];
    const float* wq    = (const float*)d_in[16];
    const float* wih   = (const float*)d_in[17];
    const float* whh   = (const float*)d_in[18];
    const float* bih   = (const float*)d_in[19];
    const float* bhh   = (const float*)d_in[20];
    const float* fg_   = (const float*)d_in[21];
    const float* fb_   = (const float*)d_in[22];
    const float* cg_   = (const float*)d_in[23];
    const float* cb_   = (const float*)d_in[24];
    const float* rg_   = (const float*)d_in[25];
    const float* rb_   = (const float*)d_in[26];
    const float* wres  = (const float*)d_in[27];
    const float* bres  = (const float*)d_in[28];
    float* out = (float*)d_out;

    k_all<<<NBLK, 256>>>(feat, featc, mask, noise, mu, ls, wgrid, bgrid,
                         wk, wv, kvg, kvb, wmlp, bmlp, qg_, qb_, wq,
                         wih, whh, bih, bhh, fg_, fb_, cg_, cb_, rg_, rb_,
                         wres, bres, out);
}

// round 12
// speedup vs baseline: 1.0316x; 1.0012x over previous
#include <cuda_runtime.h>
#include <math.h>

#define BB 16
#define KK 5
#define NN 4096
#define DD 64
#define CC 16
#define BN (BB*NN)
#define EPS_LN 1e-5f
#define SCALE 0.125f
#define NBLK 148

// ---------------- device scratch (allocation-free) ----------------
__device__ float g_featc[BN*CC];
__device__ float h_fk[BN*DD];
__device__ float h_fv[BN*DD];
__device__ float g_stK[BN*8];
__device__ float g_stV[BN*8];
__device__ float g_fg[KK*2];
__device__ float g_gsc[9];
__device__ float g_E[BB*KK*NN];
__device__ float h_qg[BB*KK*DD];
__device__ float h_qc[BB*KK*8];
__device__ float g_Tp[BB*64*KK*DD];
__device__ float g_sc[BB*64*KK*8];
__device__ float g_Cp[BB*8*KK*CC];
__device__ float g_slot[BB*KK*DD];
__device__ float g_wmT[DD*DD];
__device__ float g_wresT[DD*DD];
__device__ float g_wihT[DD*3*DD];
__device__ float g_whhT[DD*3*DD];

__device__ unsigned g_gen = 0;
__device__ unsigned g_cnt = 0;

__device__ __forceinline__ void gbar() {
    __threadfence();
    __syncthreads();
    if (threadIdx.x == 0) {
        unsigned gen = atomicAdd(&g_gen, 0u);
        if (atomicAdd(&g_cnt, 1u) == (unsigned)(NBLK - 1)) {
            atomicExch(&g_cnt, 0u);
            __threadfence();
            atomicAdd(&g_gen, 1u);
        } else {
            while (atomicAdd(&g_gen, 0u) == gen) __nanosleep(64);
        }
    }
    __syncthreads();
}

// ---------------- device stage functions ----------------

__device__ void dev_fgpos(float* sm, int k, const float* __restrict__ mask) {
    int t = threadIdx.x;
    float mx = 0.f, my = 0.f, s = 0.f;
    for (int n = t; n < NN; n += 256) {
        int h = n >> 6, w = n & 63;
        float m = mask[k*NN + n];
        mx += (-1.f + 2.f*w*(1.f/63.f))*m;
        my += (-1.f + 2.f*h*(1.f/63.f))*m;
        s += m;
    }
    float* s0 = sm; float* s1 = sm+256; float* s2 = sm+512;
    s0[t]=mx; s1[t]=my; s2[t]=s; __syncthreads();
    for (int o=128;o>0;o>>=1){
        if (t<o){ s0[t]+=s0[t+o]; s1[t]+=s1[t+o]; s2[t]+=s2[t+o]; }
        __syncthreads();
    }
    if (t==0){
        float inv = 1.f/(s2[0]+1e-5f);
        g_fg[k*2+0]=s0[0]*inv; g_fg[k*2+1]=s1[0]*inv;
    }
}

__device__ void dev_transp(float* sm, int chunk,
                           const float* __restrict__ wm, const float* __restrict__ wres,
                           const float* __restrict__ wih, const float* __restrict__ whh,
                           const float* __restrict__ wgr, const float* __restrict__ bgr) {
    int t = chunk*256 + threadIdx.x;
    if (t < 4096){
        int d = t >> 6, e = t & 63;
        g_wmT[e*64+d] = wm[t];
        g_wresT[e*64+d] = wres[t];
    }
    if (t < 12288){
        int j = t >> 6, d = t & 63;
        g_wihT[d*192+j] = wih[t];
        g_whhT[d*192+j] = whh[t];
    }
    if (chunk == 0){
        float* sm2 = sm;   // [2][9]
        int lt = threadIdx.x;
        float p9[9] = {};
        if (lt < 64){
            float w0 = wgr[lt*4+0]-wgr[lt*4+2];
            float w1 = wgr[lt*4+1]-wgr[lt*4+3];
            float bg = bgr[lt];
            p9[0]=w0; p9[1]=w1; p9[2]=bg;
            p9[3]=w0*w0; p9[4]=w0*w1; p9[5]=w1*w1;
            p9[6]=w0*bg; p9[7]=w1*bg; p9[8]=bg*bg;
            #pragma unroll
            for (int o=16;o>0;o>>=1)
                #pragma unroll
                for (int j=0;j<9;j++) p9[j] += __shfl_xor_sync(0xffffffffu,p9[j],o);
            if ((lt&31)==0)
                #pragma unroll
                for (int j=0;j<9;j++) sm2[(lt>>5)*9+j]=p9[j];
        }
        __syncthreads();
        if (lt < 9) g_gsc[lt] = sm2[lt]+sm2[9+lt];
    }
}

__device__ void dev_lnc(int bid, const float* __restrict__ x, const float* __restrict__ g,
                        const float* __restrict__ b) {
    for (int base = bid*256; base < BN*CC; base += NBLK*256){
        int idx = base + threadIdx.x;
        int lane = idx & 15;
        float v = x[idx];
        float s = v;
        #pragma unroll
        for (int o=8;o>0;o>>=1) s += __shfl_xor_sync(0xffffffffu,s,o);
        float m = s*(1.f/16.f);
        float d = v-m;
        float s2 = d*d;
        #pragma unroll
        for (int o=8;o>0;o>>=1) s2 += __shfl_xor_sync(0xffffffffu,s2,o);
        float is = rsqrtf(s2*(1.f/16.f) + EPS_LN);
        g_featc[idx] = d*is*g[lane] + b[lane];
    }
}

__device__ void dev_fkfv(float* sm, int row0, const float* __restrict__ feat,
                         const float* __restrict__ lng, const float* __restrict__ lnb,
                         const float* __restrict__ wk, const float* __restrict__ wv,
                         const float* __restrict__ wgr, const float* __restrict__ bgr) {
    float* As = sm;          // [64][65]
    float* Ws = sm + 4160;   // [64][65]
    float* gS = sm + 8320; float* bS = gS+64; float* w0S = bS+64;
    float* w1S = w0S+64; float* bgS = w1S+64;
    int t = threadIdx.x;
    __syncthreads();
    if (t < 64){
        gS[t]=lng[t]; bS[t]=lnb[t];
        w0S[t] = wgr[t*4+0]-wgr[t*4+2];
        w1S[t] = wgr[t*4+1]-wgr[t*4+3];
        bgS[t] = bgr[t];
    }
    const float4* ag = (const float4*)(feat + (size_t)row0*64);
    #pragma unroll
    for (int i=0;i<4;i++){
        int idx4 = t + i*256;
        float4 v = ag[idx4];
        int r = idx4 >> 4, d0 = (idx4 & 15)*4;
        As[r*65+d0]=v.x; As[r*65+d0+1]=v.y; As[r*65+d0+2]=v.z; As[r*65+d0+3]=v.w;
    }
    __syncthreads();
    {
        int r = t>>2, p = t&3;
        float s = 0.f;
        #pragma unroll
        for (int i=0;i<16;i++) s += As[r*65+p*16+i];
        s += __shfl_xor_sync(0xffffffffu,s,1);
        s += __shfl_xor_sync(0xffffffffu,s,2);
        float m = s*(1.f/64.f);
        float s2 = 0.f;
        #pragma unroll
        for (int i=0;i<16;i++){ float d = As[r*65+p*16+i]-m; s2 += d*d; }
        s2 += __shfl_xor_sync(0xffffffffu,s2,1);
        s2 += __shfl_xor_sync(0xffffffffu,s2,2);
        float is = rsqrtf(s2*(1.f/64.f) + EPS_LN);
        #pragma unroll
        for (int i=0;i<16;i++){
            int e = p*16+i;
            As[r*65+e] = (As[r*65+e]-m)*is*gS[e] + bS[e];
        }
    }
    int ty = t >> 4, tx = t & 15;
    int r0 = ty*4, c0 = tx*4;
    #pragma unroll
    for (int ph=0; ph<2; ph++){
        const float4* wg = (const float4*)(ph ? wv : wk);
        __syncthreads();
        #pragma unroll
        for (int i=0;i<4;i++){
            int idx4 = t + i*256;
            float4 v = wg[idx4];
            int r = idx4 >> 4, d0 = (idx4 & 15)*4;
            Ws[r*65+d0]=v.x; Ws[r*65+d0+1]=v.y; Ws[r*65+d0+2]=v.z; Ws[r*65+d0+3]=v.w;
        }
        __syncthreads();
        float acc[4][4] = {};
        #pragma unroll 4
        for (int d=0; d<64; d++){
            float a[4], w4[4];
            #pragma unroll
            for (int i=0;i<4;i++) a[i] = As[(r0+i)*65+d];
            #pragma unroll
            for (int j=0;j<4;j++) w4[j] = Ws[(c0+j)*65+d];
            #pragma unroll
            for (int i=0;i<4;i++)
                #pragma unroll
                for (int j=0;j<4;j++) acc[i][j] += a[i]*w4[j];
        }
        float* out = ph ? h_fv : h_fk;
        #pragma unroll
        for (int i=0;i<4;i++)
            *(float4*)(out + (size_t)(row0+r0+i)*64 + c0) =
                make_float4(acc[i][0],acc[i][1],acc[i][2],acc[i][3]);
        float st[4][5];
        #pragma unroll
        for (int i=0;i<4;i++){
            float s=0.f, s2=0.f, a0=0.f, a1=0.f, ab=0.f;
            #pragma unroll
            for (int j=0;j<4;j++){
                float v = acc[i][j]; int e = c0+j;
                s += v; s2 += v*v;
                a0 += v*w0S[e]; a1 += v*w1S[e]; ab += v*bgS[e];
            }
            st[i][0]=s; st[i][1]=s2; st[i][2]=a0; st[i][3]=a1; st[i][4]=ab;
        }
        #pragma unroll
        for (int o=1;o<16;o<<=1)
            #pragma unroll
            for (int i=0;i<4;i++)
                #pragma unroll
                for (int j=0;j<5;j++)
                    st[i][j] += __shfl_xor_sync(0xffffffffu, st[i][j], o);
        if (tx==0){
            float* stg = ph ? g_stV : g_stK;
            #pragma unroll
            for (int i=0;i<4;i++){
                float* p = stg + (size_t)(row0+r0+i)*8;
                p[0]=st[i][0]; p[1]=st[i][1]; p[2]=st[i][2]; p[3]=st[i][3]; p[4]=st[i][4];
            }
        }
    }
}

__device__ void dev_q0(float* sm, int row0,
                       const float* __restrict__ noise, const float* __restrict__ mu,
                       const float* __restrict__ ls,
                       const float* __restrict__ lnqg, const float* __restrict__ lnqb,
                       const float* __restrict__ wq,   const float* __restrict__ wm,
                       const float* __restrict__ bm,   const float* __restrict__ kvg,
                       const float* __restrict__ kvb,  const float* __restrict__ wgr,
                       const float* __restrict__ bgr) {
    float* WQ = sm; float* WM = sm + 4160; float* AUX = sm + 8320;
    float* lnrow = AUX; float* qrow = AUX + 256;
    float* red = AUX + 1024; float* red2 = AUX + 1032; float* redq = AUX + 1040;
    int t = threadIdx.x, x = t & 63, y = t >> 6;
    __syncthreads();
    for (int i=t;i<4096;i+=256){ WQ[(i>>6)*65+(i&63)]=wq[i]; WM[(i>>6)*65+(i&63)]=wm[i]; }
    int row = row0 + y;
    float sv = mu[x] + expf(ls[x]) * noise[row*64+x];
    g_slot[row*64+x] = sv;
    float s = sv;
    #pragma unroll
    for (int o=16;o>0;o>>=1) s += __shfl_xor_sync(0xffffffffu,s,o);
    if ((x&31)==0) red[y*2+(x>>5)]=s;
    __syncthreads();
    float m = (red[y*2]+red[y*2+1])*(1.f/64.f);
    float d = sv - m;
    float s2 = d*d;
    #pragma unroll
    for (int o=16;o>0;o>>=1) s2 += __shfl_xor_sync(0xffffffffu,s2,o);
    if ((x&31)==0) red2[y*2+(x>>5)]=s2;
    __syncthreads();
    float is = rsqrtf((red2[y*2]+red2[y*2+1])*(1.f/64.f) + EPS_LN);
    lnrow[y*64+x] = d*is*lnqg[x] + lnqb[x];
    __syncthreads();
    float q = 0.f;
    #pragma unroll 8
    for (int j=0;j<64;j++) q += lnrow[y*64+j]*WQ[x*65+j];
    qrow[y*64+x] = q;
    __syncthreads();
    float qm = 0.f;
    #pragma unroll 8
    for (int j=0;j<64;j++) qm += qrow[y*64+j]*WM[j*65+x];
    float qgv = qm*kvg[x];
    h_qg[row*64+x] = qgv;
    float w0 = wgr[x*4+0]-wgr[x*4+2];
    float w1 = wgr[x*4+1]-wgr[x*4+3];
    float c[5] = { q*bm[x] + qm*kvb[x], qgv, qgv*w0, qgv*w1, qgv*bgr[x] };
    #pragma unroll
    for (int o=16;o>0;o>>=1)
        #pragma unroll
        for (int j=0;j<5;j++) c[j] += __shfl_xor_sync(0xffffffffu,c[j],o);
    if ((x&31)==0)
        #pragma unroll
        for (int j=0;j<5;j++) redq[(y*2+(x>>5))*5+j]=c[j];
    __syncthreads();
    if (x < 5) h_qc[row*8+x] = redq[(y*2)*5+x]+redq[(y*2+1)*5+x];
}

__device__ void dev_iterA(float* sm, int seg, int b, int doB) {
    float* fvS = sm;           // [64][68]
    float* qgS = sm + 4352;    // [5][64]
    float* qcS = sm + 4672;    // [5][8]
    float* fgS = sm + 4712;    // 10
    float* gsc = sm + 4722;    // 9
    float* wSm = sm + 4731;    // 64
    float* redS = sm + 4795;   // [5][8][5]
    float* part = sm + 4995;   // [5][64]
    int n0 = seg*64, t = threadIdx.x;
    __syncthreads();
    for (int i=t;i<KK*64;i+=256) qgS[i] = __ldcg(&h_qg[b*KK*64 + i]);
    if (t < KK*8) qcS[t] = __ldcg(&h_qc[b*KK*8 + t]);
    if (t < KK*2) fgS[t] = g_fg[t];
    if (t < 9) gsc[t] = g_gsc[t];
    for (int i=t;i<KK*64;i+=256) part[i] = 0.f;
    const float4* fvg4 = (const float4*)(h_fv + (size_t)(b*NN+n0)*64);
    #pragma unroll
    for (int i=0;i<4;i++){
        int idx4 = t + i*256;
        float4 v = fvg4[idx4];
        int r = idx4>>4, c=(idx4&15)*4;
        fvS[r*68+c]=v.x; fvS[r*68+c+1]=v.y; fvS[r*68+c+2]=v.z; fvS[r*68+c+3]=v.w;
    }
    int n = t>>2, p = t&3, ng = n0 + n;
    float4 fk4[4];
    const float4* fkg = (const float4*)(h_fk + (size_t)(b*NN+ng)*64) + p*4;
    #pragma unroll
    for (int i=0;i<4;i++) fk4[i]=fkg[i];
    float stK[5], stV[5];
    if (p==0){
        const float* sk = g_stK + (size_t)(b*NN+ng)*8;
        const float* svp = g_stV + (size_t)(b*NN+ng)*8;
        #pragma unroll
        for (int i=0;i<5;i++){ stK[i]=sk[i]; stV[i]=svp[i]; }
    }
    float gx = -1.f + 2.f*(ng & 63)*(1.f/63.f);
    float gy = -1.f + 2.f*(ng >> 6)*(1.f/63.f);
    int e = t & 63, qg_ = t >> 6;
    float accT[KK];
    for (int k=0;k<KK;k++){
        __syncthreads();
        float dq = 0.f;
        #pragma unroll
        for (int i=0;i<4;i++){
            int e0 = p*16 + i*4;
            dq += fk4[i].x*qgS[k*64+e0] + fk4[i].y*qgS[k*64+e0+1]
                + fk4[i].z*qgS[k*64+e0+2] + fk4[i].w*qgS[k*64+e0+3];
        }
        dq += __shfl_xor_sync(0xffffffffu,dq,1);
        dq += __shfl_xor_sync(0xffffffffu,dq,2);
        float v5[5];
        if (p==0){
            float r0 = gx - fgS[k*2+0];
            float r1 = gy - fgS[k*2+1];
            float Sge  = gsc[0]*r0 + gsc[1]*r1 + gsc[2];
            float Sge2 = gsc[3]*r0*r0 + 2.f*gsc[4]*r0*r1 + gsc[5]*r1*r1
                       + 2.f*gsc[6]*r0 + 2.f*gsc[7]*r1 + gsc[8];
            float fkge = stK[2]*r0 + stK[3]*r1 + stK[4];
            float su  = stK[0] + Sge;
            float su2 = stK[1] + 2.f*fkge + Sge2;
            float m   = su*(1.f/64.f);
            float var = su2*(1.f/64.f) - m*m;
            float is  = rsqrtf(var + EPS_LN);
            float dqf = dq + qcS[k*8+2]*r0 + qcS[k*8+3]*r1 + qcS[k*8+4];
            float lg  = SCALE*( is*(dqf - m*qcS[k*8+1]) + qcS[k*8+0] );
            float E   = __expf(lg);
            float fvge = stV[2]*r0 + stV[3]*r1 + stV[4];
            float svv  = stV[0] + Sge;
            float sv2  = stV[1] + 2.f*fvge + Sge2;
            float mv   = svv*(1.f/64.f);
            float varv = sv2*(1.f/64.f) - mv*mv;
            float isv  = rsqrtf(varv + EPS_LN);
            float W = E*isv;
            g_E[(size_t)(b*KK+k)*NN + ng] = E;
            wSm[n] = W;
            v5[0]=W; v5[1]=W*gx; v5[2]=W*gy; v5[3]=W*mv; v5[4]=E;
        } else { v5[0]=v5[1]=v5[2]=v5[3]=v5[4]=0.f; }
        #pragma unroll
        for (int o=4;o<32;o<<=1)
            #pragma unroll
            for (int j=0;j<5;j++) v5[j] += __shfl_xor_sync(0xffffffffu,v5[j],o);
        if ((t&31)==0)
            #pragma unroll
            for (int j=0;j<5;j++) redS[(k*8+(t>>5))*5+j]=v5[j];
        __syncthreads();
        if (doB){
            float a = 0.f;
            #pragma unroll
            for (int i=0;i<16;i++){
                int nn = qg_*16 + i;
                a += wSm[nn]*fvS[nn*68+e];
            }
            accT[k] = a;
        }
    }
    __syncthreads();
    if (doB){
        for (int qq=0;qq<4;qq++){
            if (qg_==qq){
                #pragma unroll
                for (int k=0;k<KK;k++) part[k*64+e] += accT[k];
            }
            __syncthreads();
        }
        for (int i=t;i<KK*64;i+=256){
            int k=i>>6, ee=i&63;
            g_Tp[(size_t)((b*64+seg)*KK+k)*64 + ee] = part[k*64+ee];
        }
    }
    if (t < KK*5){
        int kk = t/5, j = t%5;
        float s = 0.f;
        #pragma unroll
        for (int w=0;w<8;w++) s += redS[(kk*8+w)*5+j];
        g_sc[(size_t)((b*64+seg)*KK+kk)*8 + j] = s;
    }
}

__device__ void dev_upd(float* sm, int rrow0,
                        const float* __restrict__ kvg, const float* __restrict__ kvb,
                        const float* __restrict__ bm,  const float* __restrict__ bih,
                        const float* __restrict__ bhh, const float* __restrict__ resg,
                        const float* __restrict__ resb,const float* __restrict__ bres,
                        const float* __restrict__ lnqg,const float* __restrict__ lnqb,
                        const float* __restrict__ wq,  const float* __restrict__ wm,
                        const float* __restrict__ wgr, const float* __restrict__ bgr) {
    float* WQ = sm; float* WM = sm + 4160; float* AUX = sm + 8320;
    float* lnsum = AUX; float* upds = AUX+256; float* hps = AUX+512; float* lns = AUX+768;
    float* red = AUX+1024; float* red2 = AUX+1032; float* redq = AUX+1040; float* sm5 = AUX+1080;
    int t = threadIdx.x, x = t & 63, y = t >> 6;
    __syncthreads();
    for (int i=t;i<4096;i+=256){ WQ[(i>>6)*65+(i&63)]=wq[i]; WM[(i>>6)*65+(i&63)]=wm[i]; }
    int rrow = rrow0 + y;
    int b = rrow/KK, k = rrow%KK;
    if (x < 32){
        float s5[5];
        const float* p1 = g_sc + (size_t)((b*64+x)*KK+k)*8;
        const float* p2 = g_sc + (size_t)((b*64+x+32)*KK+k)*8;
        #pragma unroll
        for (int j=0;j<5;j++) s5[j] = __ldcg(p1+j) + __ldcg(p2+j);
        #pragma unroll
        for (int o=16;o>0;o>>=1)
            #pragma unroll
            for (int j=0;j<5;j++) s5[j] += __shfl_xor_sync(0xffffffffu,s5[j],o);
        if (x==0)
            #pragma unroll
            for (int j=0;j<5;j++) sm5[y*5+j]=s5[j];
    }
    float T = 0.f;
    #pragma unroll 8
    for (int seg=0;seg<64;seg++) T += __ldcg(&g_Tp[(size_t)((b*64+seg)*KK+k)*64 + x]);
    __syncthreads();
    float C=sm5[y*5+0], A=sm5[y*5+1], Bv=sm5[y*5+2], P=sm5[y*5+3], S=sm5[y*5+4];
    float w0x = wgr[x*4+0]-wgr[x*4+2];
    float w1x = wgr[x*4+1]-wgr[x*4+3];
    float bgx = bgr[x];
    float fgx = g_fg[k*2+0], fgy = g_fg[k*2+1];
    T += w0x*(A - fgx*C) + w1x*(Bv - fgy*C) + bgx*C;
    T = (T - P)/S;
    lnsum[y*64+x] = kvg[x]*T + kvb[x];
    float hp = g_slot[rrow*64+x];
    hps[y*64+x] = hp;
    __syncthreads();
    float upd = bm[x];
    #pragma unroll 8
    for (int e=0;e<64;e++) upd += g_wmT[e*64+x]*lnsum[y*64+e];
    upds[y*64+x] = upd;
    __syncthreads();
    float gir = bih[x], giz = bih[64+x], gin = bih[128+x];
    float ghr = bhh[x], ghz = bhh[64+x], ghn = bhh[128+x];
    #pragma unroll 4
    for (int d=0;d<64;d++){
        float u = upds[y*64+d], h = hps[y*64+d];
        const float* wiT = g_wihT + d*192;
        const float* whT = g_whhT + d*192;
        gir += wiT[x]*u;     giz += wiT[64+x]*u;  gin += wiT[128+x]*u;
        ghr += whT[x]*h;     ghz += whT[64+x]*h;  ghn += whT[128+x]*h;
    }
    float rg = 1.f/(1.f+expf(-(gir+ghr)));
    float z  = 1.f/(1.f+expf(-(giz+ghz)));
    float nn = tanhf(gin + rg*ghn);
    float hnew = (1.f-z)*nn + z*hp;
    float s = hnew;
    #pragma unroll
    for (int o=16;o>0;o>>=1) s += __shfl_xor_sync(0xffffffffu,s,o);
    if ((x&31)==0) red[y*2+(x>>5)]=s;
    __syncthreads();
    float m = (red[y*2]+red[y*2+1])*(1.f/64.f);
    float dd = hnew - m;
    float s2 = dd*dd;
    #pragma unroll
    for (int o=16;o>0;o>>=1) s2 += __shfl_xor_sync(0xffffffffu,s2,o);
    if ((x&31)==0) red2[y*2+(x>>5)]=s2;
    __syncthreads();
    float is = rsqrtf((red2[y*2]+red2[y*2+1])*(1.f/64.f) + EPS_LN);
    lns[y*64+x] = dd*is*resg[x] + resb[x];
    __syncthreads();
    float outv = bres[x] + hp;
    #pragma unroll 8
    for (int e=0;e<64;e++) outv += g_wresT[e*64+x]*lns[y*64+e];
    g_slot[rrow*64+x] = outv;
    __syncthreads();
    float sq = outv;
    #pragma unroll
    for (int o=16;o>0;o>>=1) sq += __shfl_xor_sync(0xffffffffu,sq,o);
    if ((x&31)==0) red[y*2+(x>>5)]=sq;
    __syncthreads();
    float mq = (red[y*2]+red[y*2+1])*(1.f/64.f);
    float dq = outv - mq;
    float sq2 = dq*dq;
    #pragma unroll
    for (int o=16;o>0;o>>=1) sq2 += __shfl_xor_sync(0xffffffffu,sq2,o);
    if ((x&31)==0) red2[y*2+(x>>5)]=sq2;
    __syncthreads();
    float isq = rsqrtf((red2[y*2]+red2[y*2+1])*(1.f/64.f) + EPS_LN);
    lnsum[y*64+x] = dq*isq*lnqg[x] + lnqb[x];
    __syncthreads();
    float qv = 0.f;
    #pragma unroll 8
    for (int j=0;j<64;j++) qv += lnsum[y*64+j]*WQ[x*65+j];
    upds[y*64+x] = qv;
    __syncthreads();
    float qm = 0.f;
    #pragma unroll 8
    for (int j=0;j<64;j++) qm += upds[y*64+j]*WM[j*65+x];
    float qgv = qm*kvg[x];
    h_qg[rrow*64+x] = qgv;
    float c[5] = { qv*bm[x] + qm*kvb[x], qgv, qgv*w0x, qgv*w1x, qgv*bgr[x] };
    #pragma unroll
    for (int o=16;o>0;o>>=1)
        #pragma unroll
        for (int j=0;j<5;j++) c[j] += __shfl_xor_sync(0xffffffffu,c[j],o);
    if ((x&31)==0)
        #pragma unroll
        for (int j=0;j<5;j++) redq[(y*2+(x>>5))*5+j]=c[j];
    __syncthreads();
    if (x < 5) h_qc[rrow*8+x] = redq[(y*2)*5+x]+redq[(y*2+1)*5+x];
}

__device__ void dev_color(float* sm, int seg, int b) {
    float* aS = sm;            // [5][512]
    float* part2 = sm + 2560;  // [16][5][16]
    float* iS = sm + 3840;     // 5
    float* sred = sm + 3845;   // [2][5]
    int t = threadIdx.x, nbase = seg*512;
    __syncthreads();
    if (t < 64){
        float s[KK];
        #pragma unroll
        for (int k=0;k<KK;k++) s[k] = __ldcg(&g_sc[(size_t)((b*64+t)*KK+k)*8 + 4]);
        #pragma unroll
        for (int o=16;o>0;o>>=1)
            #pragma unroll
            for (int k=0;k<KK;k++) s[k] += __shfl_xor_sync(0xffffffffu,s[k],o);
        if ((t&31)==0)
            #pragma unroll
            for (int k=0;k<KK;k++) sred[(t>>5)*KK+k]=s[k];
    }
    __syncthreads();
    if (t < KK) iS[t] = 1.f/(sred[t]+sred[KK+t]);
    __syncthreads();
    for (int i=t;i<KK*512;i+=256){
        int k=i>>9, n=i&511;
        aS[i] = __ldcg(&g_E[(size_t)(b*KK+k)*NN + nbase+n])*iS[k];
    }
    __syncthreads();
    int c = t & 15, q = t >> 4;
    float acc[KK] = {};
    for (int n=q*32; n<q*32+32; n++){
        float fc = g_featc[(size_t)(b*NN+nbase+n)*CC + c];
        #pragma unroll
        for (int k=0;k<KK;k++) acc[k] += aS[k*512+n]*fc;
    }
    #pragma unroll
    for (int k=0;k<KK;k++) part2[(q*KK+k)*16+c] = acc[k];
    __syncthreads();
    if (t < KK*CC){
        int k = t>>4, cc = t&15;
        float s = 0.f;
        #pragma unroll
        for (int qq=0;qq<16;qq++) s += part2[(qq*KK+k)*16+cc];
        g_Cp[(size_t)((b*8+seg)*KK+k)*CC + cc] = s;
    }
}

__device__ void dev_attnnorm(float* sm, int k, int b, float* __restrict__ out) {
    int t = threadIdx.x, r = b*KK+k;
    size_t base = (size_t)r*NN;
    float* sredS = sm;
    float* sred = sm + 2;
    float* sred2 = sm + 10;
    __syncthreads();
    if (t < 64){
        float s = __ldcg(&g_sc[(size_t)((b*64+t)*KK+k)*8 + 4]);
        #pragma unroll
        for (int o=16;o>0;o>>=1) s += __shfl_xor_sync(0xffffffffu,s,o);
        if ((t&31)==0) sredS[t>>5]=s;
    }
    __syncthreads();
    float invS = 1.f/(sredS[0]+sredS[1]);
    float mn = 1e30f, mx = -1e30f;
    float a[16];
    #pragma unroll
    for (int j=0;j<16;j++){
        a[j] = __ldcg(&g_E[base + j*256 + t])*invS;
        mn = fminf(mn, a[j]); mx = fmaxf(mx, a[j]);
    }
    #pragma unroll
    for (int o=16;o>0;o>>=1){
        mn = fminf(mn, __shfl_xor_sync(0xffffffffu,mn,o));
        mx = fmaxf(mx, __shfl_xor_sync(0xffffffffu,mx,o));
    }
    if ((t&31)==0){ sred[t>>5]=mn; sred2[t>>5]=mx; }
    __syncthreads();
    mn = sred[0]; mx = sred2[0];
    #pragma unroll
    for (int i=1;i<8;i++){ mn = fminf(mn, sred[i]); mx = fmaxf(mx, sred2[i]); }
    float inv = 1.f/(mx-mn+1e-5f);
    #pragma unroll
    for (int j=0;j<16;j++)
        out[6560 + base + j*256 + t] = (a[j]-mn)*inv;
}

__device__ void dev_outslot(float* __restrict__ out) {
    int t = threadIdx.x;
    for (int i=t; i<80*80; i+=256){
        int r = i/80, d = i%80;
        float v;
        if (d < 64) v = __ldcg(&g_slot[r*64+d]);
        else {
            int c = d-64, b = r/KK, k = r%KK;
            v = 0.f;
            #pragma unroll
            for (int seg=0;seg<8;seg++) v += __ldcg(&g_Cp[(size_t)((b*8+seg)*KK+k)*CC + c]);
        }
        out[i] = v;
    }
    if (t < 160){
        int r = t>>1, k = r%KK;
        out[6400 + t] = g_fg[k*2 + (t&1)];
    }
}

// ---------------- the single persistent kernel ----------------

__global__ void __launch_bounds__(256, 1) k_all(
    const float* feat, const float* featc, const float* mask, const float* noise,
    const float* mu, const float* ls, const float* wgrid, const float* bgrid,
    const float* wk, const float* wv, const float* kvg, const float* kvb,
    const float* wmlp, const float* bmlp, const float* qg_, const float* qb_,
    const float* wq, const float* wih, const float* whh, const float* bih,
    const float* bhh, const float* fg_, const float* fb_, const float* cg_,
    const float* cb_, const float* rg_, const float* rb_, const float* wres,
    const float* bres, float* out)
{
    __shared__ float sm[10240];
    int bid = blockIdx.x;

    // ---- stage 0: prologue ----
    for (int g = bid; g < BN/64; g += NBLK)   // 1024 tiles (R9/R10 had 256: the bug)
        dev_fkfv(sm, g*64, feat, fg_, fb_, wk, wv, wgrid, bgrid);
    __syncthreads();
    if (bid < KK)                   dev_fgpos(sm, bid, mask);
    else if (bid < KK+48)           dev_transp(sm, bid-KK, wmlp, wres, wih, whh, wgrid, bgrid);
    else if (bid >= 60 && bid < 80) dev_q0(sm, (bid-60)*4, noise, mu, ls, qg_, qb_, wq,
                                           wmlp, bmlp, kvg, kvb, wgrid, bgrid);
    dev_lnc(bid, featc, cg_, cb_);
    gbar();

    // ---- iterations ----
    for (int it = 0; it < 4; it++){
        int doB = (it < 3) ? 1 : 0;
        for (int u = bid; u < 1024; u += NBLK)
            dev_iterA(sm, u & 63, u >> 6, doB);
        gbar();
        if (it < 3){
            if (bid < 20)
                dev_upd(sm, bid*4, kvg, kvb, bmlp, bih, bhh, rg_, rb_, bres,
                        qg_, qb_, wq, wmlp, wgrid, bgrid);
            gbar();
        }
    }

    // ---- epilogue ----
    if (bid < 128) dev_color(sm, bid & 7, bid >> 3);
    {
        int u = (bid >= 128) ? (bid - 128) : (bid + 20);
        if (u < 80) dev_attnnorm(sm, u % KK, u / KK, out);
    }
    gbar();
    if (bid == 0) dev_outslot(out);
}

// ---------------- launch ----------------

extern "C" void kernel_launch(void* const* d_in, const int* in_sizes, int n_in,
                              void* d_out, int out_size) {
    const float* feat  = (const float*)d_in[0];
    const float* featc = (const float*)d_in[1];
    const float* mask  = (const float*)d_in[2];
    const float* noise = (const float*)d_in[3];
    const float* mu    = (const float*)d_in[4];
    const float* ls    = (const float*)d_in[5];
    const float* wgrid = (const float*)d_in[6];
    const float* bgrid = (const float*)d_in[7];
    const float* wk    = (const float*)d_in[8];
    const float* wv    = (const float*)d_in[9];
    const float* kvg   = (const float*)d_in[10];
    const float* kvb   = (const float*)d_in[11];
    const float* wmlp  = (const float*)d_in[12];
    const float* bmlp  = (const float*)d_in[13];
    const float* qg_   = (const float*)d_in[14];
    const float* qb_   = (const float*)d_in[15];
    const float* wq    = (const float*)d_in[16];
    const float* wih   = (const float*)d_in[17];
    const float* whh   = (const float*)d_in[18];
    const float* bih   = (const float*)d_in[19];
    const float* bhh   = (const float*)d_in[20];
    const float* fg_   = (const float*)d_in[21];
    const float* fb_   = (const float*)d_in[22];
    const float* cg_   = (const float*)d_in[23];
    const float* cb_   = (const float*)d_in[24];
    const float* rg_   = (const float*)d_in[25];
    const float* rb_   = (const float*)d_in[26];
    const float* wres  = (const float*)d_in[27];
    const float* bres  = (const float*)d_in[28];
    float* out = (float*)d_out;

    k_all<<<NBLK, 256>>>(feat, featc, mask, noise, mu, ls, wgrid, bgrid,
                         wk, wv, kvg, kvb, wmlp, bmlp, qg_, qb_, wq,
                         wih, whh, bih, bhh, fg_, fb_, cg_, cb_, rg_, rb_,
                         wres, bres, out);
}

// round 16
// speedup vs baseline: 1.2089x; 1.1719x over previous
#include <cuda_runtime.h>
#include <math.h>

#define BB 16
#define KK 5
#define NN 4096
#define DD 64
#define CC 16
#define BN (BB*NN)
#define EPS_LN 1e-5f
#define SCALE 0.125f
#define NBLK 296

// ---------------- device scratch (allocation-free) ----------------
__device__ float g_featc[BN*CC];
__device__ float h_fk[BN*DD];
__device__ float h_fv[BN*DD];
__device__ float g_stK[BN*8];
__device__ float g_stV[BN*8];
__device__ float g_fg[KK*2];
__device__ float g_gsc[9];
__device__ float g_E[BB*KK*NN];
__device__ float h_qg[BB*KK*DD];
__device__ float h_qc[BB*KK*8];
__device__ float g_Tp[BB*64*KK*DD];
__device__ float g_sc[BB*64*KK*8];
__device__ float g_Cp[BB*8*KK*CC];
__device__ float g_slot[BB*KK*DD];
__device__ float g_wmT[DD*DD];
__device__ float g_wresT[DD*DD];
__device__ float g_wihT[DD*3*DD];
__device__ float g_whhT[DD*3*DD];

__device__ unsigned g_gen = 0;
__device__ unsigned g_cnt = 0;

__device__ __forceinline__ void gbar() {
    __threadfence();
    __syncthreads();
    if (threadIdx.x == 0) {
        unsigned gen = atomicAdd(&g_gen, 0u);
        if (atomicAdd(&g_cnt, 1u) == (unsigned)(NBLK - 1)) {
            atomicExch(&g_cnt, 0u);
            __threadfence();
            atomicAdd(&g_gen, 1u);
        } else {
            while (atomicAdd(&g_gen, 0u) == gen) __nanosleep(64);
        }
    }
    __syncthreads();
}

// ---------------- device stage functions ----------------

__device__ void dev_fgpos(float* sm, int k, const float* __restrict__ mask) {
    int t = threadIdx.x;
    float mx = 0.f, my = 0.f, s = 0.f;
    for (int n = t; n < NN; n += 256) {
        int h = n >> 6, w = n & 63;
        float m = mask[k*NN + n];
        mx += (-1.f + 2.f*w*(1.f/63.f))*m;
        my += (-1.f + 2.f*h*(1.f/63.f))*m;
        s += m;
    }
    float* s0 = sm; float* s1 = sm+256; float* s2 = sm+512;
    s0[t]=mx; s1[t]=my; s2[t]=s; __syncthreads();
    for (int o=128;o>0;o>>=1){
        if (t<o){ s0[t]+=s0[t+o]; s1[t]+=s1[t+o]; s2[t]+=s2[t+o]; }
        __syncthreads();
    }
    if (t==0){
        float inv = 1.f/(s2[0]+1e-5f);
        g_fg[k*2+0]=s0[0]*inv; g_fg[k*2+1]=s1[0]*inv;
    }
}

__device__ void dev_transp(float* sm, int chunk,
                           const float* __restrict__ wm, const float* __restrict__ wres,
                           const float* __restrict__ wih, const float* __restrict__ whh,
                           const float* __restrict__ wgr, const float* __restrict__ bgr) {
    int t = chunk*256 + threadIdx.x;
    if (t < 4096){
        int d = t >> 6, e = t & 63;
        g_wmT[e*64+d] = wm[t];
        g_wresT[e*64+d] = wres[t];
    }
    if (t < 12288){
        int j = t >> 6, d = t & 63;
        g_wihT[d*192+j] = wih[t];
        g_whhT[d*192+j] = whh[t];
    }
    if (chunk == 0){
        float* sm2 = sm;   // [2][9]
        int lt = threadIdx.x;
        float p9[9] = {};
        if (lt < 64){
            float w0 = wgr[lt*4+0]-wgr[lt*4+2];
            float w1 = wgr[lt*4+1]-wgr[lt*4+3];
            float bg = bgr[lt];
            p9[0]=w0; p9[1]=w1; p9[2]=bg;
            p9[3]=w0*w0; p9[4]=w0*w1; p9[5]=w1*w1;
            p9[6]=w0*bg; p9[7]=w1*bg; p9[8]=bg*bg;
            #pragma unroll
            for (int o=16;o>0;o>>=1)
                #pragma unroll
                for (int j=0;j<9;j++) p9[j] += __shfl_xor_sync(0xffffffffu,p9[j],o);
            if ((lt&31)==0)
                #pragma unroll
                for (int j=0;j<9;j++) sm2[(lt>>5)*9+j]=p9[j];
        }
        __syncthreads();
        if (lt < 9) g_gsc[lt] = sm2[lt]+sm2[9+lt];
    }
}

__device__ void dev_lnc(int bid, const float* __restrict__ x, const float* __restrict__ g,
                        const float* __restrict__ b) {
    for (int base = bid*256; base < BN*CC; base += NBLK*256){
        int idx = base + threadIdx.x;
        int lane = idx & 15;
        float v = x[idx];
        float s = v;
        #pragma unroll
        for (int o=8;o>0;o>>=1) s += __shfl_xor_sync(0xffffffffu,s,o);
        float m = s*(1.f/16.f);
        float d = v-m;
        float s2 = d*d;
        #pragma unroll
        for (int o=8;o>0;o>>=1) s2 += __shfl_xor_sync(0xffffffffu,s2,o);
        float is = rsqrtf(s2*(1.f/16.f) + EPS_LN);
        g_featc[idx] = d*is*g[lane] + b[lane];
    }
}

__device__ void dev_fkfv(float* sm, int row0, const float* __restrict__ feat,
                         const float* __restrict__ lng, const float* __restrict__ lnb,
                         const float* __restrict__ wk, const float* __restrict__ wv,
                         const float* __restrict__ wgr, const float* __restrict__ bgr) {
    float* As = sm;          // [64][65]
    float* Ws = sm + 4160;   // [64][65]
    float* gS = sm + 8320; float* bS = gS+64; float* w0S = bS+64;
    float* w1S = w0S+64; float* bgS = w1S+64;
    int t = threadIdx.x;
    __syncthreads();
    if (t < 64){
        gS[t]=lng[t]; bS[t]=lnb[t];
        w0S[t] = wgr[t*4+0]-wgr[t*4+2];
        w1S[t] = wgr[t*4+1]-wgr[t*4+3];
        bgS[t] = bgr[t];
    }
    const float4* ag = (const float4*)(feat + (size_t)row0*64);
    #pragma unroll
    for (int i=0;i<4;i++){
        int idx4 = t + i*256;
        float4 v = ag[idx4];
        int r = idx4 >> 4, d0 = (idx4 & 15)*4;
        As[r*65+d0]=v.x; As[r*65+d0+1]=v.y; As[r*65+d0+2]=v.z; As[r*65+d0+3]=v.w;
    }
    __syncthreads();
    {
        int r = t>>2, p = t&3;
        float s = 0.f;
        #pragma unroll
        for (int i=0;i<16;i++) s += As[r*65+p*16+i];
        s += __shfl_xor_sync(0xffffffffu,s,1);
        s += __shfl_xor_sync(0xffffffffu,s,2);
        float m = s*(1.f/64.f);
        float s2 = 0.f;
        #pragma unroll
        for (int i=0;i<16;i++){ float d = As[r*65+p*16+i]-m; s2 += d*d; }
        s2 += __shfl_xor_sync(0xffffffffu,s2,1);
        s2 += __shfl_xor_sync(0xffffffffu,s2,2);
        float is = rsqrtf(s2*(1.f/64.f) + EPS_LN);
        #pragma unroll
        for (int i=0;i<16;i++){
            int e = p*16+i;
            As[r*65+e] = (As[r*65+e]-m)*is*gS[e] + bS[e];
        }
    }
    int ty = t >> 4, tx = t & 15;
    int r0 = ty*4, c0 = tx*4;
    #pragma unroll
    for (int ph=0; ph<2; ph++){
        const float4* wg = (const float4*)(ph ? wv : wk);
        __syncthreads();
        #pragma unroll
        for (int i=0;i<4;i++){
            int idx4 = t + i*256;
            float4 v = wg[idx4];
            int r = idx4 >> 4, d0 = (idx4 & 15)*4;
            Ws[r*65+d0]=v.x; Ws[r*65+d0+1]=v.y; Ws[r*65+d0+2]=v.z; Ws[r*65+d0+3]=v.w;
        }
        __syncthreads();
        float acc[4][4] = {};
        #pragma unroll 4
        for (int d=0; d<64; d++){
            float a[4], w4[4];
            #pragma unroll
            for (int i=0;i<4;i++) a[i] = As[(r0+i)*65+d];
            #pragma unroll
            for (int j=0;j<4;j++) w4[j] = Ws[(c0+j)*65+d];
            #pragma unroll
            for (int i=0;i<4;i++)
                #pragma unroll
                for (int j=0;j<4;j++) acc[i][j] += a[i]*w4[j];
        }
        float* out = ph ? h_fv : h_fk;
        #pragma unroll
        for (int i=0;i<4;i++)
            *(float4*)(out + (size_t)(row0+r0+i)*64 + c0) =
                make_float4(acc[i][0],acc[i][1],acc[i][2],acc[i][3]);
        float st[4][5];
        #pragma unroll
        for (int i=0;i<4;i++){
            float s=0.f, s2=0.f, a0=0.f, a1=0.f, ab=0.f;
            #pragma unroll
            for (int j=0;j<4;j++){
                float v = acc[i][j]; int e = c0+j;
                s += v; s2 += v*v;
                a0 += v*w0S[e]; a1 += v*w1S[e]; ab += v*bgS[e];
            }
            st[i][0]=s; st[i][1]=s2; st[i][2]=a0; st[i][3]=a1; st[i][4]=ab;
        }
        #pragma unroll
        for (int o=1;o<16;o<<=1)
            #pragma unroll
            for (int i=0;i<4;i++)
                #pragma unroll
                for (int j=0;j<5;j++)
                    st[i][j] += __shfl_xor_sync(0xffffffffu, st[i][j], o);
        if (tx==0){
            float* stg = ph ? g_stV : g_stK;
            #pragma unroll
            for (int i=0;i<4;i++){
                float* p = stg + (size_t)(row0+r0+i)*8;
                p[0]=st[i][0]; p[1]=st[i][1]; p[2]=st[i][2]; p[3]=st[i][3]; p[4]=st[i][4];
            }
        }
    }
}

__device__ void dev_q0(float* sm, int row0,
                       const float* __restrict__ noise, const float* __restrict__ mu,
                       const float* __restrict__ ls,
                       const float* __restrict__ lnqg, const float* __restrict__ lnqb,
                       const float* __restrict__ wq,   const float* __restrict__ wm,
                       const float* __restrict__ bm,   const float* __restrict__ kvg,
                       const float* __restrict__ kvb,  const float* __restrict__ wgr,
                       const float* __restrict__ bgr) {
    float* WQ = sm; float* WM = sm + 4160; float* AUX = sm + 8320;
    float* lnrow = AUX; float* qrow = AUX + 256;
    float* red = AUX + 1024; float* red2 = AUX + 1032; float* redq = AUX + 1040;
    int t = threadIdx.x, x = t & 63, y = t >> 6;
    __syncthreads();
    for (int i=t;i<4096;i+=256){ WQ[(i>>6)*65+(i&63)]=wq[i]; WM[(i>>6)*65+(i&63)]=wm[i]; }
    int row = row0 + y;
    float sv = mu[x] + expf(ls[x]) * noise[row*64+x];
    g_slot[row*64+x] = sv;
    float s = sv;
    #pragma unroll
    for (int o=16;o>0;o>>=1) s += __shfl_xor_sync(0xffffffffu,s,o);
    if ((x&31)==0) red[y*2+(x>>5)]=s;
    __syncthreads();
    float m = (red[y*2]+red[y*2+1])*(1.f/64.f);
    float d = sv - m;
    float s2 = d*d;
    #pragma unroll
    for (int o=16;o>0;o>>=1) s2 += __shfl_xor_sync(0xffffffffu,s2,o);
    if ((x&31)==0) red2[y*2+(x>>5)]=s2;
    __syncthreads();
    float is = rsqrtf((red2[y*2]+red2[y*2+1])*(1.f/64.f) + EPS_LN);
    lnrow[y*64+x] = d*is*lnqg[x] + lnqb[x];
    __syncthreads();
    float q = 0.f;
    #pragma unroll 8
    for (int j=0;j<64;j++) q += lnrow[y*64+j]*WQ[x*65+j];
    qrow[y*64+x] = q;
    __syncthreads();
    float qm = 0.f;
    #pragma unroll 8
    for (int j=0;j<64;j++) qm += qrow[y*64+j]*WM[j*65+x];
    float qgv = qm*kvg[x];
    h_qg[row*64+x] = qgv;
    float w0 = wgr[x*4+0]-wgr[x*4+2];
    float w1 = wgr[x*4+1]-wgr[x*4+3];
    float c[5] = { q*bm[x] + qm*kvb[x], qgv, qgv*w0, qgv*w1, qgv*bgr[x] };
    #pragma unroll
    for (int o=16;o>0;o>>=1)
        #pragma unroll
        for (int j=0;j<5;j++) c[j] += __shfl_xor_sync(0xffffffffu,c[j],o);
    if ((x&31)==0)
        #pragma unroll
        for (int j=0;j<5;j++) redq[(y*2+(x>>5))*5+j]=c[j];
    __syncthreads();
    if (x < 5) h_qc[row*8+x] = redq[(y*2)*5+x]+redq[(y*2+1)*5+x];
}

__device__ void dev_iterA(float* sm, int seg, int b, int doB) {
    float* fvS = sm;           // [64][68]
    float* qgS = sm + 4352;    // [5][64]
    float* qcS = sm + 4672;    // [5][8]
    float* fgS = sm + 4712;    // 10
    float* gsc = sm + 4722;    // 9
    float* wSm = sm + 4731;    // 64
    float* redS = sm + 4795;   // [5][8][5]
    float* part = sm + 4995;   // [5][64]
    int n0 = seg*64, t = threadIdx.x;
    __syncthreads();
    for (int i=t;i<KK*64;i+=256) qgS[i] = __ldcg(&h_qg[b*KK*64 + i]);
    if (t < KK*8) qcS[t] = __ldcg(&h_qc[b*KK*8 + t]);
    if (t < KK*2) fgS[t] = g_fg[t];
    if (t < 9) gsc[t] = g_gsc[t];
    for (int i=t;i<KK*64;i+=256) part[i] = 0.f;
    const float4* fvg4 = (const float4*)(h_fv + (size_t)(b*NN+n0)*64);
    #pragma unroll
    for (int i=0;i<4;i++){
        int idx4 = t + i*256;
        float4 v = fvg4[idx4];
        int r = idx4>>4, c=(idx4&15)*4;
        fvS[r*68+c]=v.x; fvS[r*68+c+1]=v.y; fvS[r*68+c+2]=v.z; fvS[r*68+c+3]=v.w;
    }
    int n = t>>2, p = t&3, ng = n0 + n;
    float4 fk4[4];
    const float4* fkg = (const float4*)(h_fk + (size_t)(b*NN+ng)*64) + p*4;
    #pragma unroll
    for (int i=0;i<4;i++) fk4[i]=fkg[i];
    float stK[5], stV[5];
    if (p==0){
        const float* sk = g_stK + (size_t)(b*NN+ng)*8;
        const float* svp = g_stV + (size_t)(b*NN+ng)*8;
        #pragma unroll
        for (int i=0;i<5;i++){ stK[i]=sk[i]; stV[i]=svp[i]; }
    }
    float gx = -1.f + 2.f*(ng & 63)*(1.f/63.f);
    float gy = -1.f + 2.f*(ng >> 6)*(1.f/63.f);
    int e = t & 63, qg_ = t >> 6;
    float accT[KK];
    for (int k=0;k<KK;k++){
        __syncthreads();
        float dq = 0.f;
        #pragma unroll
        for (int i=0;i<4;i++){
            int e0 = p*16 + i*4;
            dq += fk4[i].x*qgS[k*64+e0] + fk4[i].y*qgS[k*64+e0+1]
                + fk4[i].z*qgS[k*64+e0+2] + fk4[i].w*qgS[k*64+e0+3];
        }
        dq += __shfl_xor_sync(0xffffffffu,dq,1);
        dq += __shfl_xor_sync(0xffffffffu,dq,2);
        float v5[5];
        if (p==0){
            float r0 = gx - fgS[k*2+0];
            float r1 = gy - fgS[k*2+1];
            float Sge  = gsc[0]*r0 + gsc[1]*r1 + gsc[2];
            float Sge2 = gsc[3]*r0*r0 + 2.f*gsc[4]*r0*r1 + gsc[5]*r1*r1
                       + 2.f*gsc[6]*r0 + 2.f*gsc[7]*r1 + gsc[8];
            float fkge = stK[2]*r0 + stK[3]*r1 + stK[4];
            float su  = stK[0] + Sge;
            float su2 = stK[1] + 2.f*fkge + Sge2;
            float m   = su*(1.f/64.f);
            float var = su2*(1.f/64.f) - m*m;
            float is  = rsqrtf(var + EPS_LN);
            float dqf = dq + qcS[k*8+2]*r0 + qcS[k*8+3]*r1 + qcS[k*8+4];
            float lg  = SCALE*( is*(dqf - m*qcS[k*8+1]) + qcS[k*8+0] );
            float E   = __expf(lg);
            float fvge = stV[2]*r0 + stV[3]*r1 + stV[4];
            float svv  = stV[0] + Sge;
            float sv2  = stV[1] + 2.f*fvge + Sge2;
            float mv   = svv*(1.f/64.f);
            float varv = sv2*(1.f/64.f) - mv*mv;
            float isv  = rsqrtf(varv + EPS_LN);
            float W = E*isv;
            g_E[(size_t)(b*KK+k)*NN + ng] = E;
            wSm[n] = W;
            v5[0]=W; v5[1]=W*gx; v5[2]=W*gy; v5[3]=W*mv; v5[4]=E;
        } else { v5[0]=v5[1]=v5[2]=v5[3]=v5[4]=0.f; }
        #pragma unroll
        for (int o=4;o<32;o<<=1)
            #pragma unroll
            for (int j=0;j<5;j++) v5[j] += __shfl_xor_sync(0xffffffffu,v5[j],o);
        if ((t&31)==0)
            #pragma unroll
            for (int j=0;j<5;j++) redS[(k*8+(t>>5))*5+j]=v5[j];
        __syncthreads();
        if (doB){
            float a = 0.f;
            #pragma unroll
            for (int i=0;i<16;i++){
                int nn = qg_*16 + i;
                a += wSm[nn]*fvS[nn*68+e];
            }
            accT[k] = a;
        }
    }
    __syncthreads();
    if (doB){
        for (int qq=0;qq<4;qq++){
            if (qg_==qq){
                #pragma unroll
                for (int k=0;k<KK;k++) part[k*64+e] += accT[k];
            }
            __syncthreads();
        }
        for (int i=t;i<KK*64;i+=256){
            int k=i>>6, ee=i&63;
            g_Tp[(size_t)((b*64+seg)*KK+k)*64 + ee] = part[k*64+ee];
        }
    }
    if (t < KK*5){
        int kk = t/5, j = t%5;
        float s = 0.f;
        #pragma unroll
        for (int w=0;w<8;w++) s += redS[(kk*8+w)*5+j];
        g_sc[(size_t)((b*64+seg)*KK+kk)*8 + j] = s;
    }
}

__device__ void dev_upd(float* sm, int rrow0,
                        const float* __restrict__ kvg, const float* __restrict__ kvb,
                        const float* __restrict__ bm,  const float* __restrict__ bih,
                        const float* __restrict__ bhh, const float* __restrict__ resg,
                        const float* __restrict__ resb,const float* __restrict__ bres,
                        const float* __restrict__ lnqg,const float* __restrict__ lnqb,
                        const float* __restrict__ wq,  const float* __restrict__ wm,
                        const float* __restrict__ wgr, const float* __restrict__ bgr) {
    float* WQ = sm; float* WM = sm + 4160; float* AUX = sm + 8320;
    float* lnsum = AUX; float* upds = AUX+256; float* hps = AUX+512; float* lns = AUX+768;
    float* red = AUX+1024; float* red2 = AUX+1032; float* redq = AUX+1040; float* sm5 = AUX+1080;
    int t = threadIdx.x, x = t & 63, y = t >> 6;
    __syncthreads();
    for (int i=t;i<4096;i+=256){ WQ[(i>>6)*65+(i&63)]=wq[i]; WM[(i>>6)*65+(i&63)]=wm[i]; }
    int rrow = rrow0 + y;
    int b = rrow/KK, k = rrow%KK;
    if (x < 32){
        float s5[5];
        const float* p1 = g_sc + (size_t)((b*64+x)*KK+k)*8;
        const float* p2 = g_sc + (size_t)((b*64+x+32)*KK+k)*8;
        #pragma unroll
        for (int j=0;j<5;j++) s5[j] = __ldcg(p1+j) + __ldcg(p2+j);
        #pragma unroll
        for (int o=16;o>0;o>>=1)
            #pragma unroll
            for (int j=0;j<5;j++) s5[j] += __shfl_xor_sync(0xffffffffu,s5[j],o);
        if (x==0)
            #pragma unroll
            for (int j=0;j<5;j++) sm5[y*5+j]=s5[j];
    }
    float T = 0.f;
    #pragma unroll 8
    for (int seg=0;seg<64;seg++) T += __ldcg(&g_Tp[(size_t)((b*64+seg)*KK+k)*64 + x]);
    __syncthreads();
    float C=sm5[y*5+0], A=sm5[y*5+1], Bv=sm5[y*5+2], P=sm5[y*5+3], S=sm5[y*5+4];
    float w0x = wgr[x*4+0]-wgr[x*4+2];
    float w1x = wgr[x*4+1]-wgr[x*4+3];
    float bgx = bgr[x];
    float fgx = g_fg[k*2+0], fgy = g_fg[k*2+1];
    T += w0x*(A - fgx*C) + w1x*(Bv - fgy*C) + bgx*C;
    T = (T - P)/S;
    lnsum[y*64+x] = kvg[x]*T + kvb[x];
    float hp = g_slot[rrow*64+x];
    hps[y*64+x] = hp;
    __syncthreads();
    float upd = bm[x];
    #pragma unroll 8
    for (int e=0;e<64;e++) upd += g_wmT[e*64+x]*lnsum[y*64+e];
    upds[y*64+x] = upd;
    __syncthreads();
    float gir = bih[x], giz = bih[64+x], gin = bih[128+x];
    float ghr = bhh[x], ghz = bhh[64+x], ghn = bhh[128+x];
    #pragma unroll 4
    for (int d=0;d<64;d++){
        float u = upds[y*64+d], h = hps[y*64+d];
        const float* wiT = g_wihT + d*192;
        const float* whT = g_whhT + d*192;
        gir += wiT[x]*u;     giz += wiT[64+x]*u;  gin += wiT[128+x]*u;
        ghr += whT[x]*h;     ghz += whT[64+x]*h;  ghn += whT[128+x]*h;
    }
    float rg = 1.f/(1.f+expf(-(gir+ghr)));
    float z  = 1.f/(1.f+expf(-(giz+ghz)));
    float nn = tanhf(gin + rg*ghn);
    float hnew = (1.f-z)*nn + z*hp;
    float s = hnew;
    #pragma unroll
    for (int o=16;o>0;o>>=1) s += __shfl_xor_sync(0xffffffffu,s,o);
    if ((x&31)==0) red[y*2+(x>>5)]=s;
    __syncthreads();
    float m = (red[y*2]+red[y*2+1])*(1.f/64.f);
    float dd = hnew - m;
    float s2 = dd*dd;
    #pragma unroll
    for (int o=16;o>0;o>>=1) s2 += __shfl_xor_sync(0xffffffffu,s2,o);
    if ((x&31)==0) red2[y*2+(x>>5)]=s2;
    __syncthreads();
    float is = rsqrtf((red2[y*2]+red2[y*2+1])*(1.f/64.f) + EPS_LN);
    lns[y*64+x] = dd*is*resg[x] + resb[x];
    __syncthreads();
    float outv = bres[x] + hp;
    #pragma unroll 8
    for (int e=0;e<64;e++) outv += g_wresT[e*64+x]*lns[y*64+e];
    g_slot[rrow*64+x] = outv;
    __syncthreads();
    float sq = outv;
    #pragma unroll
    for (int o=16;o>0;o>>=1) sq += __shfl_xor_sync(0xffffffffu,sq,o);
    if ((x&31)==0) red[y*2+(x>>5)]=sq;
    __syncthreads();
    float mq = (red[y*2]+red[y*2+1])*(1.f/64.f);
    float dq = outv - mq;
    float sq2 = dq*dq;
    #pragma unroll
    for (int o=16;o>0;o>>=1) sq2 += __shfl_xor_sync(0xffffffffu,sq2,o);
    if ((x&31)==0) red2[y*2+(x>>5)]=sq2;
    __syncthreads();
    float isq = rsqrtf((red2[y*2]+red2[y*2+1])*(1.f/64.f) + EPS_LN);
    lnsum[y*64+x] = dq*isq*lnqg[x] + lnqb[x];
    __syncthreads();
    float qv = 0.f;
    #pragma unroll 8
    for (int j=0;j<64;j++) qv += lnsum[y*64+j]*WQ[x*65+j];
    upds[y*64+x] = qv;
    __syncthreads();
    float qm = 0.f;
    #pragma unroll 8
    for (int j=0;j<64;j++) qm += upds[y*64+j]*WM[j*65+x];
    float qgv = qm*kvg[x];
    h_qg[rrow*64+x] = qgv;
    float c[5] = { qv*bm[x] + qm*kvb[x], qgv, qgv*w0x, qgv*w1x, qgv*bgr[x] };
    #pragma unroll
    for (int o=16;o>0;o>>=1)
        #pragma unroll
        for (int j=0;j<5;j++) c[j] += __shfl_xor_sync(0xffffffffu,c[j],o);
    if ((x&31)==0)
        #pragma unroll
        for (int j=0;j<5;j++) redq[(y*2+(x>>5))*5+j]=c[j];
    __syncthreads();
    if (x < 5) h_qc[rrow*8+x] = redq[(y*2)*5+x]+redq[(y*2+1)*5+x];
}

__device__ void dev_color(float* sm, int seg, int b) {
    float* aS = sm;            // [5][512]
    float* part2 = sm + 2560;  // [16][5][16]
    float* iS = sm + 3840;     // 5
    float* sred = sm + 3845;   // [2][5]
    int t = threadIdx.x, nbase = seg*512;
    __syncthreads();
    if (t < 64){
        float s[KK];
        #pragma unroll
        for (int k=0;k<KK;k++) s[k] = __ldcg(&g_sc[(size_t)((b*64+t)*KK+k)*8 + 4]);
        #pragma unroll
        for (int o=16;o>0;o>>=1)
            #pragma unroll
            for (int k=0;k<KK;k++) s[k] += __shfl_xor_sync(0xffffffffu,s[k],o);
        if ((t&31)==0)
            #pragma unroll
            for (int k=0;k<KK;k++) sred[(t>>5)*KK+k]=s[k];
    }
    __syncthreads();
    if (t < KK) iS[t] = 1.f/(sred[t]+sred[KK+t]);
    __syncthreads();
    for (int i=t;i<KK*512;i+=256){
        int k=i>>9, n=i&511;
        aS[i] = __ldcg(&g_E[(size_t)(b*KK+k)*NN + nbase+n])*iS[k];
    }
    __syncthreads();
    int c = t & 15, q = t >> 4;
    float acc[KK] = {};
    for (int n=q*32; n<q*32+32; n++){
        float fc = g_featc[(size_t)(b*NN+nbase+n)*CC + c];
        #pragma unroll
        for (int k=0;k<KK;k++) acc[k] += aS[k*512+n]*fc;
    }
    #pragma unroll
    for (int k=0;k<KK;k++) part2[(q*KK+k)*16+c] = acc[k];
    __syncthreads();
    if (t < KK*CC){
        int k = t>>4, cc = t&15;
        float s = 0.f;
        #pragma unroll
        for (int qq=0;qq<16;qq++) s += part2[(qq*KK+k)*16+cc];
        g_Cp[(size_t)((b*8+seg)*KK+k)*CC + cc] = s;
    }
}

__device__ void dev_attnnorm(float* sm, int k, int b, float* __restrict__ out) {
    int t = threadIdx.x, r = b*KK+k;
    size_t base = (size_t)r*NN;
    float* sredS = sm;
    float* sred = sm + 2;
    float* sred2 = sm + 10;
    __syncthreads();
    if (t < 64){
        float s = __ldcg(&g_sc[(size_t)((b*64+t)*KK+k)*8 + 4]);
        #pragma unroll
        for (int o=16;o>0;o>>=1) s += __shfl_xor_sync(0xffffffffu,s,o);
        if ((t&31)==0) sredS[t>>5]=s;
    }
    __syncthreads();
    float invS = 1.f/(sredS[0]+sredS[1]);
    float mn = 1e30f, mx = -1e30f;
    float a[16];
    #pragma unroll
    for (int j=0;j<16;j++){
        a[j] = __ldcg(&g_E[base + j*256 + t])*invS;
        mn = fminf(mn, a[j]); mx = fmaxf(mx, a[j]);
    }
    #pragma unroll
    for (int o=16;o>0;o>>=1){
        mn = fminf(mn, __shfl_xor_sync(0xffffffffu,mn,o));
        mx = fmaxf(mx, __shfl_xor_sync(0xffffffffu,mx,o));
    }
    if ((t&31)==0){ sred[t>>5]=mn; sred2[t>>5]=mx; }
    __syncthreads();
    mn = sred[0]; mx = sred2[0];
    #pragma unroll
    for (int i=1;i<8;i++){ mn = fminf(mn, sred[i]); mx = fmaxf(mx, sred2[i]); }
    float inv = 1.f/(mx-mn+1e-5f);
    #pragma unroll
    for (int j=0;j<16;j++)
        out[6560 + base + j*256 + t] = (a[j]-mn)*inv;
}

__device__ void dev_outslot(float* __restrict__ out) {
    int t = threadIdx.x;
    for (int i=t; i<80*80; i+=256){
        int r = i/80, d = i%80;
        float v;
        if (d < 64) v = __ldcg(&g_slot[r*64+d]);
        else {
            int c = d-64, b = r/KK, k = r%KK;
            v = 0.f;
            #pragma unroll
            for (int seg=0;seg<8;seg++) v += __ldcg(&g_Cp[(size_t)((b*8+seg)*KK+k)*CC + c]);
        }
        out[i] = v;
    }
    if (t < 160){
        int r = t>>1, k = r%KK;
        out[6400 + t] = g_fg[k*2 + (t&1)];
    }
}

// ---------------- the single persistent kernel (2 CTAs/SM) ----------------

__global__ void __launch_bounds__(256, 2) k_all(
    const float* feat, const float* featc, const float* mask, const float* noise,
    const float* mu, const float* ls, const float* wgrid, const float* bgrid,
    const float* wk, const float* wv, const float* kvg, const float* kvb,
    const float* wmlp, const float* bmlp, const float* qg_, const float* qb_,
    const float* wq, const float* wih, const float* whh, const float* bih,
    const float* bhh, const float* fg_, const float* fb_, const float* cg_,
    const float* cb_, const float* rg_, const float* rb_, const float* wres,
    const float* bres, float* out)
{
    __shared__ float sm[10240];
    int bid = blockIdx.x;

    // ---- stage 0: prologue ----
    for (int g = bid; g < BN/64; g += NBLK)
        dev_fkfv(sm, g*64, feat, fg_, fb_, wk, wv, wgrid, bgrid);
    __syncthreads();
    if (bid < KK)                   dev_fgpos(sm, bid, mask);
    else if (bid < KK+48)           dev_transp(sm, bid-KK, wmlp, wres, wih, whh, wgrid, bgrid);
    else if (bid >= 60 && bid < 80) dev_q0(sm, (bid-60)*4, noise, mu, ls, qg_, qb_, wq,
                                           wmlp, bmlp, kvg, kvb, wgrid, bgrid);
    dev_lnc(bid, featc, cg_, cb_);
    gbar();

    // ---- iterations ----
    for (int it = 0; it < 4; it++){
        int doB = (it < 3) ? 1 : 0;
        for (int u = bid; u < 1024; u += NBLK)
            dev_iterA(sm, u & 63, u >> 6, doB);
        gbar();
        if (it < 3){
            if (bid < 20)
                dev_upd(sm, bid*4, kvg, kvb, bmlp, bih, bhh, rg_, rb_, bres,
                        qg_, qb_, wq, wmlp, wgrid, bgrid);
            gbar();
        }
    }

    // ---- epilogue (clean disjoint block->task map for NBLK=296) ----
    if (bid < 128) dev_color(sm, bid & 7, bid >> 3);
    else if (bid < 208) { int u = bid - 128; dev_attnnorm(sm, u % KK, u / KK, out); }
    gbar();
    if (bid == 0) dev_outslot(out);
}

// ---------------- launch ----------------

extern "C" void kernel_launch(void* const* d_in, const int* in_sizes, int n_in,
                              void* d_out, int out_size) {
    const float* feat  = (const float*)d_in[0];
    const float* featc = (const float*)d_in[1];
    const float* mask  = (const float*)d_in[2];
    const float* noise = (const float*)d_in[3];
    const float* mu    = (const float*)d_in[4];
    const float* ls    = (const float*)d_in[5];
    const float* wgrid = (const float*)d_in[6];
    const float* bgrid = (const float*)d_in[7];
    const float* wk    = (const float*)d_in[8];
    const float* wv    = (const float*)d_in[9];
    const float* kvg   = (const float*)d_in[10];
    const float* kvb   = (const float*)d_in[11];
    const float* wmlp  = (const float*)d_in[12];
    const float* bmlp  = (const float*)d_in[13];
    const float* qg_   = (const float*)d_in[14];
    const float* qb_   = (const float*)d_in[15];
    const float* wq    = (const float*)d_in[16];
    const float* wih   = (const float*)d_in[17];
    const float* whh   = (const float*)d_in[18];
    const float* bih   = (const float*)d_in[19];
    const float* bhh   = (const float*)d_in[20];
    const float* fg_   = (const float*)d_in[21];
    const float* fb_   = (const float*)d_in[22];
    const float* cg_   = (const float*)d_in[23];
    const float* cb_   = (const float*)d_in[24];
    const float* rg_   = (const float*)d_in[25];
    const float* rb_   = (const float*)d_in[26];
    const float* wres  = (const float*)d_in[27];
    const float* bres  = (const float*)d_in[28];
    float* out = (float*)d_out;

    k_all<<<NBLK, 256>>>(feat, featc, mask, noise, mu, ls, wgrid, bgrid,
                         wk, wv, kvg, kvb, wmlp, bmlp, qg_, qb_, wq,
                         wih, whh, bih, bhh, fg_, fb_, cg_, cb_, rg_, rb_,
                         wres, bres, out);
}

// round 17
// speedup vs baseline: 1.2229x; 1.0116x over previous
#include <cuda_runtime.h>
#include <math.h>

#define BB 16
#define KK 5
#define NN 4096
#define DD 64
#define CC 16
#define BN (BB*NN)
#define EPS_LN 1e-5f
#define SCALE 0.125f
#define NBLK 256

// ---------------- device scratch (allocation-free) ----------------
__device__ float g_featc[BN*CC];
__device__ float h_fk[BN*DD];
__device__ float h_fv[BN*DD];
__device__ float g_stK[BN*8];
__device__ float g_stV[BN*8];
__device__ float g_fg[KK*2];
__device__ float g_gsc[9];
__device__ float g_E[BB*KK*NN];
__device__ float h_qg[BB*KK*DD];
__device__ float h_qc[BB*KK*8];
__device__ float g_Tp[BB*64*KK*DD];
__device__ float g_sc[BB*64*KK*8];
__device__ float g_Cp[BB*8*KK*CC];
__device__ float g_slot[BB*KK*DD];
__device__ float g_wmT[DD*DD];
__device__ float g_wresT[DD*DD];
__device__ float g_wihT[DD*3*DD];
__device__ float g_whhT[DD*3*DD];

__device__ unsigned g_gen = 0;
__device__ unsigned g_cnt = 0;

__device__ __forceinline__ void gbar() {
    __threadfence();
    __syncthreads();
    if (threadIdx.x == 0) {
        unsigned gen = atomicAdd(&g_gen, 0u);
        if (atomicAdd(&g_cnt, 1u) == (unsigned)(NBLK - 1)) {
            atomicExch(&g_cnt, 0u);
            __threadfence();
            atomicAdd(&g_gen, 1u);
        } else {
            while (atomicAdd(&g_gen, 0u) == gen) __nanosleep(64);
        }
    }
    __syncthreads();
}

// ---------------- device stage functions ----------------

__device__ void dev_fgpos(float* sm, int k, const float* __restrict__ mask) {
    int t = threadIdx.x;
    float mx = 0.f, my = 0.f, s = 0.f;
    for (int n = t; n < NN; n += 256) {
        int h = n >> 6, w = n & 63;
        float m = mask[k*NN + n];
        mx += (-1.f + 2.f*w*(1.f/63.f))*m;
        my += (-1.f + 2.f*h*(1.f/63.f))*m;
        s += m;
    }
    float* s0 = sm; float* s1 = sm+256; float* s2 = sm+512;
    s0[t]=mx; s1[t]=my; s2[t]=s; __syncthreads();
    for (int o=128;o>0;o>>=1){
        if (t<o){ s0[t]+=s0[t+o]; s1[t]+=s1[t+o]; s2[t]+=s2[t+o]; }
        __syncthreads();
    }
    if (t==0){
        float inv = 1.f/(s2[0]+1e-5f);
        g_fg[k*2+0]=s0[0]*inv; g_fg[k*2+1]=s1[0]*inv;
    }
}

__device__ void dev_transp(float* sm, int chunk,
                           const float* __restrict__ wm, const float* __restrict__ wres,
                           const float* __restrict__ wih, const float* __restrict__ whh,
                           const float* __restrict__ wgr, const float* __restrict__ bgr) {
    int t = chunk*256 + threadIdx.x;
    if (t < 4096){
        int d = t >> 6, e = t & 63;
        g_wmT[e*64+d] = wm[t];
        g_wresT[e*64+d] = wres[t];
    }
    if (t < 12288){
        int j = t >> 6, d = t & 63;
        g_wihT[d*192+j] = wih[t];
        g_whhT[d*192+j] = whh[t];
    }
    if (chunk == 0){
        float* sm2 = sm;   // [2][9]
        int lt = threadIdx.x;
        float p9[9] = {};
        if (lt < 64){
            float w0 = wgr[lt*4+0]-wgr[lt*4+2];
            float w1 = wgr[lt*4+1]-wgr[lt*4+3];
            float bg = bgr[lt];
            p9[0]=w0; p9[1]=w1; p9[2]=bg;
            p9[3]=w0*w0; p9[4]=w0*w1; p9[5]=w1*w1;
            p9[6]=w0*bg; p9[7]=w1*bg; p9[8]=bg*bg;
            #pragma unroll
            for (int o=16;o>0;o>>=1)
                #pragma unroll
                for (int j=0;j<9;j++) p9[j] += __shfl_xor_sync(0xffffffffu,p9[j],o);
            if ((lt&31)==0)
                #pragma unroll
                for (int j=0;j<9;j++) sm2[(lt>>5)*9+j]=p9[j];
        }
        __syncthreads();
        if (lt < 9) g_gsc[lt] = sm2[lt]+sm2[9+lt];
    }
}

__device__ void dev_lnc(int bid, const float* __restrict__ x, const float* __restrict__ g,
                        const float* __restrict__ b) {
    for (int base = bid*256; base < BN*CC; base += NBLK*256){
        int idx = base + threadIdx.x;
        int lane = idx & 15;
        float v = x[idx];
        float s = v;
        #pragma unroll
        for (int o=8;o>0;o>>=1) s += __shfl_xor_sync(0xffffffffu,s,o);
        float m = s*(1.f/16.f);
        float d = v-m;
        float s2 = d*d;
        #pragma unroll
        for (int o=8;o>0;o>>=1) s2 += __shfl_xor_sync(0xffffffffu,s2,o);
        float is = rsqrtf(s2*(1.f/16.f) + EPS_LN);
        g_featc[idx] = d*is*g[lane] + b[lane];
    }
}

__device__ void dev_fkfv(float* sm, int row0, const float* __restrict__ feat,
                         const float* __restrict__ lng, const float* __restrict__ lnb,
                         const float* __restrict__ wk, const float* __restrict__ wv,
                         const float* __restrict__ wgr, const float* __restrict__ bgr) {
    float* As = sm;          // [64][65]
    float* Ws = sm + 4160;   // [64][65]
    float* gS = sm + 8320; float* bS = gS+64; float* w0S = bS+64;
    float* w1S = w0S+64; float* bgS = w1S+64;
    int t = threadIdx.x;
    __syncthreads();
    if (t < 64){
        gS[t]=lng[t]; bS[t]=lnb[t];
        w0S[t] = wgr[t*4+0]-wgr[t*4+2];
        w1S[t] = wgr[t*4+1]-wgr[t*4+3];
        bgS[t] = bgr[t];
    }
    const float4* ag = (const float4*)(feat + (size_t)row0*64);
    #pragma unroll
    for (int i=0;i<4;i++){
        int idx4 = t + i*256;
        float4 v = ag[idx4];
        int r = idx4 >> 4, d0 = (idx4 & 15)*4;
        As[r*65+d0]=v.x; As[r*65+d0+1]=v.y; As[r*65+d0+2]=v.z; As[r*65+d0+3]=v.w;
    }
    __syncthreads();
    {
        int r = t>>2, p = t&3;
        float s = 0.f;
        #pragma unroll
        for (int i=0;i<16;i++) s += As[r*65+p*16+i];
        s += __shfl_xor_sync(0xffffffffu,s,1);
        s += __shfl_xor_sync(0xffffffffu,s,2);
        float m = s*(1.f/64.f);
        float s2 = 0.f;
        #pragma unroll
        for (int i=0;i<16;i++){ float d = As[r*65+p*16+i]-m; s2 += d*d; }
        s2 += __shfl_xor_sync(0xffffffffu,s2,1);
        s2 += __shfl_xor_sync(0xffffffffu,s2,2);
        float is = rsqrtf(s2*(1.f/64.f) + EPS_LN);
        #pragma unroll
        for (int i=0;i<16;i++){
            int e = p*16+i;
            As[r*65+e] = (As[r*65+e]-m)*is*gS[e] + bS[e];
        }
    }
    int ty = t >> 4, tx = t & 15;
    int r0 = ty*4, c0 = tx*4;
    #pragma unroll
    for (int ph=0; ph<2; ph++){
        const float4* wg = (const float4*)(ph ? wv : wk);
        __syncthreads();
        #pragma unroll
        for (int i=0;i<4;i++){
            int idx4 = t + i*256;
            float4 v = wg[idx4];
            int r = idx4 >> 4, d0 = (idx4 & 15)*4;
            Ws[r*65+d0]=v.x; Ws[r*65+d0+1]=v.y; Ws[r*65+d0+2]=v.z; Ws[r*65+d0+3]=v.w;
        }
        __syncthreads();
        float acc[4][4] = {};
        #pragma unroll 4
        for (int d=0; d<64; d++){
            float a[4], w4[4];
            #pragma unroll
            for (int i=0;i<4;i++) a[i] = As[(r0+i)*65+d];
            #pragma unroll
            for (int j=0;j<4;j++) w4[j] = Ws[(c0+j)*65+d];
            #pragma unroll
            for (int i=0;i<4;i++)
                #pragma unroll
                for (int j=0;j<4;j++) acc[i][j] += a[i]*w4[j];
        }
        float* out = ph ? h_fv : h_fk;
        #pragma unroll
        for (int i=0;i<4;i++)
            *(float4*)(out + (size_t)(row0+r0+i)*64 + c0) =
                make_float4(acc[i][0],acc[i][1],acc[i][2],acc[i][3]);
        float st[4][5];
        #pragma unroll
        for (int i=0;i<4;i++){
            float s=0.f, s2=0.f, a0=0.f, a1=0.f, ab=0.f;
            #pragma unroll
            for (int j=0;j<4;j++){
                float v = acc[i][j]; int e = c0+j;
                s += v; s2 += v*v;
                a0 += v*w0S[e]; a1 += v*w1S[e]; ab += v*bgS[e];
            }
            st[i][0]=s; st[i][1]=s2; st[i][2]=a0; st[i][3]=a1; st[i][4]=ab;
        }
        #pragma unroll
        for (int o=1;o<16;o<<=1)
            #pragma unroll
            for (int i=0;i<4;i++)
                #pragma unroll
                for (int j=0;j<5;j++)
                    st[i][j] += __shfl_xor_sync(0xffffffffu, st[i][j], o);
        if (tx==0){
            float* stg = ph ? g_stV : g_stK;
            #pragma unroll
            for (int i=0;i<4;i++){
                float* p = stg + (size_t)(row0+r0+i)*8;
                p[0]=st[i][0]; p[1]=st[i][1]; p[2]=st[i][2]; p[3]=st[i][3]; p[4]=st[i][4];
            }
        }
    }
}

__device__ void dev_q0(float* sm, int row0,
                       const float* __restrict__ noise, const float* __restrict__ mu,
                       const float* __restrict__ ls,
                       const float* __restrict__ lnqg, const float* __restrict__ lnqb,
                       const float* __restrict__ wq,   const float* __restrict__ wm,
                       const float* __restrict__ bm,   const float* __restrict__ kvg,
                       const float* __restrict__ kvb,  const float* __restrict__ wgr,
                       const float* __restrict__ bgr) {
    float* WQ = sm; float* WM = sm + 4160; float* AUX = sm + 8320;
    float* lnrow = AUX; float* qrow = AUX + 256;
    float* red = AUX + 1024; float* red2 = AUX + 1032; float* redq = AUX + 1040;
    int t = threadIdx.x, x = t & 63, y = t >> 6;
    __syncthreads();
    for (int i=t;i<4096;i+=256){ WQ[(i>>6)*65+(i&63)]=wq[i]; WM[(i>>6)*65+(i&63)]=wm[i]; }
    int row = row0 + y;
    float sv = mu[x] + expf(ls[x]) * noise[row*64+x];
    g_slot[row*64+x] = sv;
    float s = sv;
    #pragma unroll
    for (int o=16;o>0;o>>=1) s += __shfl_xor_sync(0xffffffffu,s,o);
    if ((x&31)==0) red[y*2+(x>>5)]=s;
    __syncthreads();
    float m = (red[y*2]+red[y*2+1])*(1.f/64.f);
    float d = sv - m;
    float s2 = d*d;
    #pragma unroll
    for (int o=16;o>0;o>>=1) s2 += __shfl_xor_sync(0xffffffffu,s2,o);
    if ((x&31)==0) red2[y*2+(x>>5)]=s2;
    __syncthreads();
    float is = rsqrtf((red2[y*2]+red2[y*2+1])*(1.f/64.f) + EPS_LN);
    lnrow[y*64+x] = d*is*lnqg[x] + lnqb[x];
    __syncthreads();
    float q = 0.f;
    #pragma unroll 8
    for (int j=0;j<64;j++) q += lnrow[y*64+j]*WQ[x*65+j];
    qrow[y*64+x] = q;
    __syncthreads();
    float qm = 0.f;
    #pragma unroll 8
    for (int j=0;j<64;j++) qm += qrow[y*64+j]*WM[j*65+x];
    float qgv = qm*kvg[x];
    h_qg[row*64+x] = qgv;
    float w0 = wgr[x*4+0]-wgr[x*4+2];
    float w1 = wgr[x*4+1]-wgr[x*4+3];
    float c[5] = { q*bm[x] + qm*kvb[x], qgv, qgv*w0, qgv*w1, qgv*bgr[x] };
    #pragma unroll
    for (int o=16;o>0;o>>=1)
        #pragma unroll
        for (int j=0;j<5;j++) c[j] += __shfl_xor_sync(0xffffffffu,c[j],o);
    if ((x&31)==0)
        #pragma unroll
        for (int j=0;j<5;j++) redq[(y*2+(x>>5))*5+j]=c[j];
    __syncthreads();
    if (x < 5) h_qc[row*8+x] = redq[(y*2)*5+x]+redq[(y*2+1)*5+x];
}

// Restructured: phase A stores W for ALL k, single fused phase B. 2 syncs/unit.
__device__ void dev_iterA(float* sm, int seg, int b, int doB) {
    float* fvS = sm;           // [64][68] = 4352
    float* qgS = sm + 4352;    // [5][64]  = 320
    float* qcS = sm + 4672;    // [5][8]   = 40
    float* fgS = sm + 4712;    // 10
    float* gsc = sm + 4722;    // 9
    float* wSm = sm + 4736;    // [5][68]  = 340
    float* redS = sm + 5076;   // [5][8][5] = 200
    float* part = sm + 5276;   // [5][64]  = 320
    int n0 = seg*64, t = threadIdx.x;
    __syncthreads();
    for (int i=t;i<KK*64;i+=256) qgS[i] = __ldcg(&h_qg[b*KK*64 + i]);
    if (t < KK*8) qcS[t] = __ldcg(&h_qc[b*KK*8 + t]);
    if (t < KK*2) fgS[t] = g_fg[t];
    if (t < 9) gsc[t] = g_gsc[t];
    const float4* fvg4 = (const float4*)(h_fv + (size_t)(b*NN+n0)*64);
    #pragma unroll
    for (int i=0;i<4;i++){
        int idx4 = t + i*256;
        float4 v = fvg4[idx4];
        int r = idx4>>4, c=(idx4&15)*4;
        fvS[r*68+c]=v.x; fvS[r*68+c+1]=v.y; fvS[r*68+c+2]=v.z; fvS[r*68+c+3]=v.w;
    }
    int n = t>>2, p = t&3, ng = n0 + n;
    float4 fk4[4];
    const float4* fkg = (const float4*)(h_fk + (size_t)(b*NN+ng)*64) + p*4;
    #pragma unroll
    for (int i=0;i<4;i++) fk4[i]=fkg[i];
    float stK[5], stV[5];
    if (p==0){
        const float* sk = g_stK + (size_t)(b*NN+ng)*8;
        const float* svp = g_stV + (size_t)(b*NN+ng)*8;
        #pragma unroll
        for (int i=0;i<5;i++){ stK[i]=sk[i]; stV[i]=svp[i]; }
    }
    float gx = -1.f + 2.f*(ng & 63)*(1.f/63.f);
    float gy = -1.f + 2.f*(ng >> 6)*(1.f/63.f);
    __syncthreads();
    // ---- phase A: logits/E/W for all k (no block syncs inside) ----
    for (int k=0;k<KK;k++){
        float dq = 0.f;
        #pragma unroll
        for (int i=0;i<4;i++){
            int e0 = p*16 + i*4;
            dq += fk4[i].x*qgS[k*64+e0] + fk4[i].y*qgS[k*64+e0+1]
                + fk4[i].z*qgS[k*64+e0+2] + fk4[i].w*qgS[k*64+e0+3];
        }
        dq += __shfl_xor_sync(0xffffffffu,dq,1);
        dq += __shfl_xor_sync(0xffffffffu,dq,2);
        float v5[5];
        if (p==0){
            float r0 = gx - fgS[k*2+0];
            float r1 = gy - fgS[k*2+1];
            float Sge  = gsc[0]*r0 + gsc[1]*r1 + gsc[2];
            float Sge2 = gsc[3]*r0*r0 + 2.f*gsc[4]*r0*r1 + gsc[5]*r1*r1
                       + 2.f*gsc[6]*r0 + 2.f*gsc[7]*r1 + gsc[8];
            float fkge = stK[2]*r0 + stK[3]*r1 + stK[4];
            float su  = stK[0] + Sge;
            float su2 = stK[1] + 2.f*fkge + Sge2;
            float m   = su*(1.f/64.f);
            float var = su2*(1.f/64.f) - m*m;
            float is  = rsqrtf(var + EPS_LN);
            float dqf = dq + qcS[k*8+2]*r0 + qcS[k*8+3]*r1 + qcS[k*8+4];
            float lg  = SCALE*( is*(dqf - m*qcS[k*8+1]) + qcS[k*8+0] );
            float E   = __expf(lg);
            float fvge = stV[2]*r0 + stV[3]*r1 + stV[4];
            float svv  = stV[0] + Sge;
            float sv2  = stV[1] + 2.f*fvge + Sge2;
            float mv   = svv*(1.f/64.f);
            float varv = sv2*(1.f/64.f) - mv*mv;
            float isv  = rsqrtf(varv + EPS_LN);
            float W = E*isv;
            g_E[(size_t)(b*KK+k)*NN + ng] = E;
            wSm[k*68+n] = W;
            v5[0]=W; v5[1]=W*gx; v5[2]=W*gy; v5[3]=W*mv; v5[4]=E;
        } else { v5[0]=v5[1]=v5[2]=v5[3]=v5[4]=0.f; }
        #pragma unroll
        for (int o=4;o<32;o<<=1)
            #pragma unroll
            for (int j=0;j<5;j++) v5[j] += __shfl_xor_sync(0xffffffffu,v5[j],o);
        if ((t&31)==0)
            #pragma unroll
            for (int j=0;j<5;j++) redS[(k*8+(t>>5))*5+j]=v5[j];
    }
    __syncthreads();
    // ---- phase B: fused W @ fv for all k (fv read once per nn) ----
    if (doB){
        int e = t & 63, qg_ = t >> 6;
        float accT[KK] = {};
        #pragma unroll
        for (int i=0;i<16;i++){
            int nn = qg_*16 + i;
            float fv = fvS[nn*68+e];
            #pragma unroll
            for (int k=0;k<KK;k++) accT[k] += wSm[k*68+nn]*fv;
        }
        for (int i=t;i<KK*64;i+=256) part[i] = 0.f;
        __syncthreads();
        for (int qq=0;qq<4;qq++){
            if (qg_==qq){
                #pragma unroll
                for (int k=0;k<KK;k++) part[k*64+e] += accT[k];
            }
            __syncthreads();
        }
        for (int i=t;i<KK*64;i+=256){
            int k=i>>6, ee=i&63;
            g_Tp[(size_t)((b*64+seg)*KK+k)*64 + ee] = part[k*64+ee];
        }
    }
    if (t < KK*5){
        int kk = t/5, j = t%5;
        float s = 0.f;
        #pragma unroll
        for (int w=0;w<8;w++) s += redS[(kk*8+w)*5+j];
        g_sc[(size_t)((b*64+seg)*KK+kk)*8 + j] = s;
    }
}

__device__ void dev_upd(float* sm, int rrow0,
                        const float* __restrict__ kvg, const float* __restrict__ kvb,
                        const float* __restrict__ bm,  const float* __restrict__ bih,
                        const float* __restrict__ bhh, const float* __restrict__ resg,
                        const float* __restrict__ resb,const float* __restrict__ bres,
                        const float* __restrict__ lnqg,const float* __restrict__ lnqb,
                        const float* __restrict__ wq,  const float* __restrict__ wm,
                        const float* __restrict__ wgr, const float* __restrict__ bgr) {
    float* WQ = sm; float* WM = sm + 4160; float* AUX = sm + 8320;
    float* lnsum = AUX; float* upds = AUX+256; float* hps = AUX+512; float* lns = AUX+768;
    float* red = AUX+1024; float* red2 = AUX+1032; float* redq = AUX+1040; float* sm5 = AUX+1080;
    int t = threadIdx.x, x = t & 63, y = t >> 6;
    __syncthreads();
    for (int i=t;i<4096;i+=256){ WQ[(i>>6)*65+(i&63)]=wq[i]; WM[(i>>6)*65+(i&63)]=wm[i]; }
    int rrow = rrow0 + y;
    int b = rrow/KK, k = rrow%KK;
    if (x < 32){
        float s5[5];
        const float* p1 = g_sc + (size_t)((b*64+x)*KK+k)*8;
        const float* p2 = g_sc + (size_t)((b*64+x+32)*KK+k)*8;
        #pragma unroll
        for (int j=0;j<5;j++) s5[j] = __ldcg(p1+j) + __ldcg(p2+j);
        #pragma unroll
        for (int o=16;o>0;o>>=1)
            #pragma unroll
            for (int j=0;j<5;j++) s5[j] += __shfl_xor_sync(0xffffffffu,s5[j],o);
        if (x==0)
            #pragma unroll
            for (int j=0;j<5;j++) sm5[y*5+j]=s5[j];
    }
    float T = 0.f;
    #pragma unroll 8
    for (int seg=0;seg<64;seg++) T += __ldcg(&g_Tp[(size_t)((b*64+seg)*KK+k)*64 + x]);
    __syncthreads();
    float C=sm5[y*5+0], A=sm5[y*5+1], Bv=sm5[y*5+2], P=sm5[y*5+3], S=sm5[y*5+4];
    float w0x = wgr[x*4+0]-wgr[x*4+2];
    float w1x = wgr[x*4+1]-wgr[x*4+3];
    float bgx = bgr[x];
    float fgx = g_fg[k*2+0], fgy = g_fg[k*2+1];
    T += w0x*(A - fgx*C) + w1x*(Bv - fgy*C) + bgx*C;
    T = (T - P)/S;
    lnsum[y*64+x] = kvg[x]*T + kvb[x];
    float hp = g_slot[rrow*64+x];
    hps[y*64+x] = hp;
    __syncthreads();
    float upd = bm[x];
    #pragma unroll 8
    for (int e=0;e<64;e++) upd += g_wmT[e*64+x]*lnsum[y*64+e];
    upds[y*64+x] = upd;
    __syncthreads();
    float gir = bih[x], giz = bih[64+x], gin = bih[128+x];
    float ghr = bhh[x], ghz = bhh[64+x], ghn = bhh[128+x];
    #pragma unroll 4
    for (int d=0;d<64;d++){
        float u = upds[y*64+d], h = hps[y*64+d];
        const float* wiT = g_wihT + d*192;
        const float* whT = g_whhT + d*192;
        gir += wiT[x]*u;     giz += wiT[64+x]*u;  gin += wiT[128+x]*u;
        ghr += whT[x]*h;     ghz += whT[64+x]*h;  ghn += whT[128+x]*h;
    }
    float rg = 1.f/(1.f+expf(-(gir+ghr)));
    float z  = 1.f/(1.f+expf(-(giz+ghz)));
    float nn = tanhf(gin + rg*ghn);
    float hnew = (1.f-z)*nn + z*hp;
    float s = hnew;
    #pragma unroll
    for (int o=16;o>0;o>>=1) s += __shfl_xor_sync(0xffffffffu,s,o);
    if ((x&31)==0) red[y*2+(x>>5)]=s;
    __syncthreads();
    float m = (red[y*2]+red[y*2+1])*(1.f/64.f);
    float dd = hnew - m;
    float s2 = dd*dd;
    #pragma unroll
    for (int o=16;o>0;o>>=1) s2 += __shfl_xor_sync(0xffffffffu,s2,o);
    if ((x&31)==0) red2[y*2+(x>>5)]=s2;
    __syncthreads();
    float is = rsqrtf((red2[y*2]+red2[y*2+1])*(1.f/64.f) + EPS_LN);
    lns[y*64+x] = dd*is*resg[x] + resb[x];
    __syncthreads();
    float outv = bres[x] + hp;
    #pragma unroll 8
    for (int e=0;e<64;e++) outv += g_wresT[e*64+x]*lns[y*64+e];
    g_slot[rrow*64+x] = outv;
    __syncthreads();
    float sq = outv;
    #pragma unroll
    for (int o=16;o>0;o>>=1) sq += __shfl_xor_sync(0xffffffffu,sq,o);
    if ((x&31)==0) red[y*2+(x>>5)]=sq;
    __syncthreads();
    float mq = (red[y*2]+red[y*2+1])*(1.f/64.f);
    float dq = outv - mq;
    float sq2 = dq*dq;
    #pragma unroll
    for (int o=16;o>0;o>>=1) sq2 += __shfl_xor_sync(0xffffffffu,sq2,o);
    if ((x&31)==0) red2[y*2+(x>>5)]=sq2;
    __syncthreads();
    float isq = rsqrtf((red2[y*2]+red2[y*2+1])*(1.f/64.f) + EPS_LN);
    lnsum[y*64+x] = dq*isq*lnqg[x] + lnqb[x];
    __syncthreads();
    float qv = 0.f;
    #pragma unroll 8
    for (int j=0;j<64;j++) qv += lnsum[y*64+j]*WQ[x*65+j];
    upds[y*64+x] = qv;
    __syncthreads();
    float qm = 0.f;
    #pragma unroll 8
    for (int j=0;j<64;j++) qm += upds[y*64+j]*WM[j*65+x];
    float qgv = qm*kvg[x];
    h_qg[rrow*64+x] = qgv;
    float c[5] = { qv*bm[x] + qm*kvb[x], qgv, qgv*w0x, qgv*w1x, qgv*bgr[x] };
    #pragma unroll
    for (int o=16;o>0;o>>=1)
        #pragma unroll
        for (int j=0;j<5;j++) c[j] += __shfl_xor_sync(0xffffffffu,c[j],o);
    if ((x&31)==0)
        #pragma unroll
        for (int j=0;j<5;j++) redq[(y*2+(x>>5))*5+j]=c[j];
    __syncthreads();
    if (x < 5) h_qc[rrow*8+x] = redq[(y*2)*5+x]+redq[(y*2+1)*5+x];
}

__device__ void dev_color(float* sm, int seg, int b) {
    float* aS = sm;            // [5][512]
    float* part2 = sm + 2560;  // [16][5][16]
    float* iS = sm + 3840;     // 5
    float* sred = sm + 3845;   // [2][5]
    int t = threadIdx.x, nbase = seg*512;
    __syncthreads();
    if (t < 64){
        float s[KK];
        #pragma unroll
        for (int k=0;k<KK;k++) s[k] = __ldcg(&g_sc[(size_t)((b*64+t)*KK+k)*8 + 4]);
        #pragma unroll
        for (int o=16;o>0;o>>=1)
            #pragma unroll
            for (int k=0;k<KK;k++) s[k] += __shfl_xor_sync(0xffffffffu,s[k],o);
        if ((t&31)==0)
            #pragma unroll
            for (int k=0;k<KK;k++) sred[(t>>5)*KK+k]=s[k];
    }
    __syncthreads();
    if (t < KK) iS[t] = 1.f/(sred[t]+sred[KK+t]);
    __syncthreads();
    for (int i=t;i<KK*512;i+=256){
        int k=i>>9, n=i&511;
        aS[i] = __ldcg(&g_E[(size_t)(b*KK+k)*NN + nbase+n])*iS[k];
    }
    __syncthreads();
    int c = t & 15, q = t >> 4;
    float acc[KK] = {};
    for (int n=q*32; n<q*32+32; n++){
        float fc = g_featc[(size_t)(b*NN+nbase+n)*CC + c];
        #pragma unroll
        for (int k=0;k<KK;k++) acc[k] += aS[k*512+n]*fc;
    }
    #pragma unroll
    for (int k=0;k<KK;k++) part2[(q*KK+k)*16+c] = acc[k];
    __syncthreads();
    if (t < KK*CC){
        int k = t>>4, cc = t&15;
        float s = 0.f;
        #pragma unroll
        for (int qq=0;qq<16;qq++) s += part2[(qq*KK+k)*16+cc];
        g_Cp[(size_t)((b*8+seg)*KK+k)*CC + cc] = s;
    }
}

__device__ void dev_attnnorm(float* sm, int k, int b, float* __restrict__ out) {
    int t = threadIdx.x, r = b*KK+k;
    size_t base = (size_t)r*NN;
    float* sredS = sm;
    float* sred = sm + 2;
    float* sred2 = sm + 10;
    __syncthreads();
    if (t < 64){
        float s = __ldcg(&g_sc[(size_t)((b*64+t)*KK+k)*8 + 4]);
        #pragma unroll
        for (int o=16;o>0;o>>=1) s += __shfl_xor_sync(0xffffffffu,s,o);
        if ((t&31)==0) sredS[t>>5]=s;
    }
    __syncthreads();
    float invS = 1.f/(sredS[0]+sredS[1]);
    float mn = 1e30f, mx = -1e30f;
    float a[16];
    #pragma unroll
    for (int j=0;j<16;j++){
        a[j] = __ldcg(&g_E[base + j*256 + t])*invS;
        mn = fminf(mn, a[j]); mx = fmaxf(mx, a[j]);
    }
    #pragma unroll
    for (int o=16;o>0;o>>=1){
        mn = fminf(mn, __shfl_xor_sync(0xffffffffu,mn,o));
        mx = fmaxf(mx, __shfl_xor_sync(0xffffffffu,mx,o));
    }
    if ((t&31)==0){ sred[t>>5]=mn; sred2[t>>5]=mx; }
    __syncthreads();
    mn = sred[0]; mx = sred2[0];
    #pragma unroll
    for (int i=1;i<8;i++){ mn = fminf(mn, sred[i]); mx = fmaxf(mx, sred2[i]); }
    float inv = 1.f/(mx-mn+1e-5f);
    #pragma unroll
    for (int j=0;j<16;j++)
        out[6560 + base + j*256 + t] = (a[j]-mn)*inv;
}

__device__ void dev_outslot(float* __restrict__ out) {
    int t = threadIdx.x;
    for (int i=t; i<80*80; i+=256){
        int r = i/80, d = i%80;
        float v;
        if (d < 64) v = __ldcg(&g_slot[r*64+d]);
        else {
            int c = d-64, b = r/KK, k = r%KK;
            v = 0.f;
            #pragma unroll
            for (int seg=0;seg<8;seg++) v += __ldcg(&g_Cp[(size_t)((b*8+seg)*KK+k)*CC + c]);
        }
        out[i] = v;
    }
    if (t < 160){
        int r = t>>1, k = r%KK;
        out[6400 + t] = g_fg[k*2 + (t&1)];
    }
}

// ---------------- the single persistent kernel (2 CTAs/SM) ----------------

__global__ void __launch_bounds__(256, 2) k_all(
    const float* feat, const float* featc, const float* mask, const float* noise,
    const float* mu, const float* ls, const float* wgrid, const float* bgrid,
    const float* wk, const float* wv, const float* kvg, const float* kvb,
    const float* wmlp, const float* bmlp, const float* qg_, const float* qb_,
    const float* wq, const float* wih, const float* whh, const float* bih,
    const float* bhh, const float* fg_, const float* fb_, const float* cg_,
    const float* cb_, const float* rg_, const float* rb_, const float* wres,
    const float* bres, float* out)
{
    __shared__ float sm[10240];
    int bid = blockIdx.x;

    // ---- stage 0: prologue ----
    for (int g = bid; g < BN/64; g += NBLK)
        dev_fkfv(sm, g*64, feat, fg_, fb_, wk, wv, wgrid, bgrid);
    __syncthreads();
    if (bid < KK)                   dev_fgpos(sm, bid, mask);
    else if (bid < KK+48)           dev_transp(sm, bid-KK, wmlp, wres, wih, whh, wgrid, bgrid);
    else if (bid >= 60 && bid < 80) dev_q0(sm, (bid-60)*4, noise, mu, ls, qg_, qb_, wq,
                                           wmlp, bmlp, kvg, kvb, wgrid, bgrid);
    dev_lnc(bid, featc, cg_, cb_);
    gbar();

    // ---- iterations (1024 units / 256 blocks = exactly 4 each) ----
    for (int it = 0; it < 4; it++){
        int doB = (it < 3) ? 1 : 0;
        for (int u = bid; u < 1024; u += NBLK)
            dev_iterA(sm, u & 63, u >> 6, doB);
        gbar();
        if (it < 3){
            if (bid < 20)
                dev_upd(sm, bid*4, kvg, kvb, bmlp, bih, bhh, rg_, rb_, bres,
                        qg_, qb_, wq, wmlp, wgrid, bgrid);
            gbar();
        }
    }

    // ---- epilogue ----
    if (bid < 128) dev_color(sm, bid & 7, bid >> 3);
    else if (bid < 208) { int u = bid - 128; dev_attnnorm(sm, u % KK, u / KK, out); }
    gbar();
    if (bid == 0) dev_outslot(out);
}

// ---------------- launch ----------------

extern "C" void kernel_launch(void* const* d_in, const int* in_sizes, int n_in,
                              void* d_out, int out_size) {
    const float* feat  = (const float*)d_in[0];
    const float* featc = (const float*)d_in[1];
    const float* mask  = (const float*)d_in[2];
    const float* noise = (const float*)d_in[3];
    const float* mu    = (const float*)d_in[4];
    const float* ls    = (const float*)d_in[5];
    const float* wgrid = (const float*)d_in[6];
    const float* bgrid = (const float*)d_in[7];
    const float* wk    = (const float*)d_in[8];
    const float* wv    = (const float*)d_in[9];
    const float* kvg   = (const float*)d_in[10];
    const float* kvb   = (const float*)d_in[11];
    const float* wmlp  = (const float*)d_in[12];
    const float* bmlp  = (const float*)d_in[13];
    const float* qg_   = (const float*)d_in[14];
    const float* qb_   = (const float*)d_in[15];
    const float* wq    = (const float*)d_in[16];
    const float* wih   = (const float*)d_in[17];
    const float* whh   = (const float*)d_in[18];
    const float* bih   = (const float*)d_in[19];
    const float* bhh   = (const float*)d_in[20];
    const float* fg_   = (const float*)d_in[21];
    const float* fb_   = (const float*)d_in[22];
    const float* cg_   = (const float*)d_in[23];
    const float* cb_   = (const float*)d_in[24];
    const float* rg_   = (const float*)d_in[25];
    const float* rb_   = (const float*)d_in[26];
    const float* wres  = (const float*)d_in[27];
    const float* bres  = (const float*)d_in[28];
    float* out = (float*)d_out;

    k_all<<<NBLK, 256>>>(feat, featc, mask, noise, mu, ls, wgrid, bgrid,
                         wk, wv, kvg, kvb, wmlp, bmlp, qg_, qb_, wq,
                         wih, whh, bih, bhh, fg_, fb_, cg_, cb_, rg_, rb_,
                         wres, bres, out);
}